// round 9
// baseline (speedup 1.0000x reference)
#include <cuda_runtime.h>
#include <cuda_bf16.h>
#include <math.h>
#include <stdint.h>

// Problem constants
#define BATCH   2
#define NTXT    2048
#define T_MEDIA 4
#define M_MEDIA 256
#define TM_TOT  1024
#define DIM     1024
#define HEADS   16
#define DH      64
#define EPS     1e-5f

#define MQ  (BATCH * NTXT)     // 4096

// ---------------------------------------------------------------------------
// Scratch (device globals; no allocations allowed)
// ---------------------------------------------------------------------------
__device__ float g_impart[BATCH * 32 * DIM];       // image partial col sums
__device__ float g_imgmean[BATCH * DIM];           // mean over tm of image
__device__ float g_vmean [BATCH * DIM];            // imgmean @ Wv (exact)
__device__ float g_omean [BATCH * DIM];            // vmean @ Wo
__device__ int   g_tt    [MQ];                     // txt_time
__device__ int   g_act   [MQ];                     // active rows (tt in [1..4])
__device__ int   g_nact;
__device__ float g_qact  [MQ * DIM];               // q rows for active queries
__device__ float g_oact  [MQ * DIM];               // attention out for active queries

// ---------------------------------------------------------------------------
// Warp-split GEMV core: y[n0..n0+64) = x[0..1024) @ W[.,n0..n0+64)
// 256 threads: warp w handles k in [128w,128w+128); lane covers 2 n.
// ---------------------------------------------------------------------------
__device__ __forceinline__ void gemv_chunk(const float* __restrict__ W, int ldw,
                                           const float* __restrict__ x,
                                           float* __restrict__ part,
                                           int n0, int w, int lane) {
    float a0 = 0.0f, a1 = 0.0f;
    int n = n0 + lane * 2;
    const float* Wp = W + (size_t)(w * 128) * ldw + n;
    const float* xp = x + w * 128;
    #pragma unroll 8
    for (int kk = 0; kk < 128; kk++) {
        float xv = xp[kk];
        float2 wv = *(const float2*)(Wp + (size_t)kk * ldw);
        a0 = fmaf(xv, wv.x, a0);
        a1 = fmaf(xv, wv.y, a1);
    }
    part[w * 64 + lane * 2]     = a0;
    part[w * 64 + lane * 2 + 1] = a1;
}

// ---------------------------------------------------------------------------
// Inclusive scan of locations -> txt_time. One block of 1024 per batch.
// ---------------------------------------------------------------------------
__global__ void scan_kernel(const int* __restrict__ loc) {
    int b = blockIdx.x;
    int tid = threadIdx.x;
    if (b == 0 && tid == 0) g_nact = 0;
    __shared__ int s[1024];
    const int* L = loc + b * NTXT;
    int a0 = L[2 * tid];
    int a1 = L[2 * tid + 1];
    int v0 = a0, v1 = a0 + a1;
    s[tid] = v1;
    __syncthreads();
    for (int off = 1; off < 1024; off <<= 1) {
        int t = (tid >= off) ? s[tid - off] : 0;
        __syncthreads();
        s[tid] += t;
        __syncthreads();
    }
    int excl = s[tid] - v1;
    g_tt[b * NTXT + 2 * tid]     = excl + v0;
    g_tt[b * NTXT + 2 * tid + 1] = excl + v1;
}

__global__ void compact_kernel() {
    int row = blockIdx.x * 1024 + threadIdx.x;
    int tt = g_tt[row];
    if (tt >= 1 && tt <= T_MEDIA) {
        int slot = atomicAdd(&g_nact, 1);
        g_act[slot] = row;
    }
}

// ---------------------------------------------------------------------------
// Block reduce helper (256 threads)
// ---------------------------------------------------------------------------
__device__ __forceinline__ float blockReduceSum256(float v, float* red) {
    #pragma unroll
    for (int o = 16; o; o >>= 1) v += __shfl_xor_sync(0xffffffffu, v, o);
    int lane = threadIdx.x & 31, w = threadIdx.x >> 5;
    if (lane == 0) red[w] = v;
    __syncthreads();
    float r = (threadIdx.x < 8) ? red[threadIdx.x] : 0.0f;
    if (threadIdx.x < 32) {
        #pragma unroll
        for (int o = 4; o; o >>= 1) r += __shfl_xor_sync(0xffffffffu, r, o);
        if (threadIdx.x == 0) red[0] = r;
    }
    __syncthreads();
    float out = red[0];
    __syncthreads();
    return out;
}

// ---------------------------------------------------------------------------
// image column partial sums + mean
// ---------------------------------------------------------------------------
__global__ void imgmean_part(const float* __restrict__ image) {
    int c  = blockIdx.x * 256 + threadIdx.x;
    int ry = blockIdx.y;                    // 0..31
    int b  = blockIdx.z;
    const float* base = image + ((size_t)(b * TM_TOT + ry * 32)) * DIM + c;
    float s = 0.0f;
    #pragma unroll 8
    for (int j = 0; j < 32; j++) s += base[(size_t)j * DIM];
    g_impart[(b * 32 + ry) * DIM + c] = s;
}

__global__ void imgmean_final() {
    int c = blockIdx.x * 256 + threadIdx.x;
    int b = blockIdx.y;
    float s = 0.0f;
    #pragma unroll
    for (int r = 0; r < 32; r++) s += g_impart[(b * 32 + r) * DIM + c];
    g_imgmean[b * DIM + c] = s * (1.0f / TM_TOT);
}

// vmean[b] = imgmean[b] @ Wv   (Wv = Wkv columns [1024,2048), ldw 2048)
__global__ __launch_bounds__(256)
void vmean_kernel(const float* __restrict__ Wkv) {
    __shared__ float x[DIM];
    __shared__ float part[8 * 64];
    int tid = threadIdx.x, lane = tid & 31, w = tid >> 5;
    int n0 = blockIdx.x * 64;
    int b = blockIdx.y;
    ((float4*)x)[tid] = ((const float4*)(g_imgmean + b * DIM))[tid];
    __syncthreads();
    gemv_chunk(Wkv + DIM, 2 * DIM, x, part, n0, w, lane);
    __syncthreads();
    if (tid < 64) {
        float acc = 0.0f;
        #pragma unroll
        for (int ww = 0; ww < 8; ww++) acc += part[ww * 64 + tid];
        g_vmean[b * DIM + n0 + tid] = acc;
    }
}

// omean[b] = vmean[b] @ Wo
__global__ __launch_bounds__(256)
void omean_kernel(const float* __restrict__ Wo) {
    __shared__ float x[DIM];
    __shared__ float part[8 * 64];
    int tid = threadIdx.x, lane = tid & 31, w = tid >> 5;
    int n0 = blockIdx.x * 64;
    int b = blockIdx.y;
    ((float4*)x)[tid] = ((const float4*)(g_vmean + b * DIM))[tid];
    __syncthreads();
    gemv_chunk(Wo, DIM, x, part, n0, w, lane);
    __syncthreads();
    if (tid < 64) {
        float acc = 0.0f;
        #pragma unroll
        for (int ww = 0; ww < 8; ww++) acc += part[ww * 64 + tid];
        g_omean[b * DIM + n0 + tid] = acc;
    }
}

// ---------------------------------------------------------------------------
// Fused LayerNorm + q GEMV for active rows.  grid (16 n-chunks, 64 slots)
// ---------------------------------------------------------------------------
__global__ __launch_bounds__(256)
void qact_kernel(const float* __restrict__ text,
                 const float* __restrict__ gamma,
                 const float* __restrict__ beta,
                 const float* __restrict__ Wq) {
    __shared__ float x[DIM];
    __shared__ float red[8];
    __shared__ float part[8 * 64];
    int tid = threadIdx.x, lane = tid & 31, w = tid >> 5;
    int n0 = blockIdx.x * 64;
    int nact = g_nact;
    for (int s = blockIdx.y; s < nact; s += gridDim.y) {
        int row = g_act[s];
        float4 v = ((const float4*)(text + (size_t)row * DIM))[tid];
        float sm = v.x + v.y + v.z + v.w;
        float mu = blockReduceSum256(sm, red) * (1.0f / DIM);
        float dx = v.x - mu, dy = v.y - mu, dz = v.z - mu, dw = v.w - mu;
        float var = blockReduceSum256(dx * dx + dy * dy + dz * dz + dw * dw, red) * (1.0f / DIM);
        float inv = rsqrtf(var + EPS);
        float4 g = ((const float4*)gamma)[tid];
        float4 bt = ((const float4*)beta)[tid];
        x[4 * tid + 0] = dx * inv * g.x + bt.x;
        x[4 * tid + 1] = dy * inv * g.y + bt.y;
        x[4 * tid + 2] = dz * inv * g.z + bt.z;
        x[4 * tid + 3] = dw * inv * g.w + bt.w;
        __syncthreads();
        gemv_chunk(Wq, DIM, x, part, n0, w, lane);
        __syncthreads();
        if (tid < 64) {
            float acc = 0.0f;
            #pragma unroll
            for (int ww = 0; ww < 8; ww++) acc += part[ww * 64 + tid];
            g_qact[(size_t)s * DIM + n0 + tid] = acc;
        }
        __syncthreads();
    }
}

// ---------------------------------------------------------------------------
// Fused reassociated attention per (slot, head-group of 4). grid (64, 4).
//   qk[h][c]  = sum_d q[h*64+d] * Wk[c][hg*256 + h*64 + d]     (k never formed)
//   S[h][j]   = scale * sum_c qk[h][c] * img[j0+j][c]
//   p = softmax_j(S)
//   w[h][c]   = sum_j p[h][j] * img[j0+j][c]   (stored over qk)
//   o[n]      = sum_c w[h(n)][c] * Wv[c][n]                    (v never formed)
// ---------------------------------------------------------------------------
__global__ __launch_bounds__(256)
void attn_fused(const float* __restrict__ image,
                const float* __restrict__ Wkv) {
    __shared__ float qs[256];          // q slice for this head group (1 KB)
    __shared__ float qkw[4][DIM];      // qk, reused as w (16 KB)
    __shared__ float S[4][M_MEDIA];    // 4 KB
    __shared__ float part[8 * 64];     // o-phase partials (2 KB)
    int tid = threadIdx.x;
    int lane = tid & 31, w8 = tid >> 5;
    int hg = blockIdx.y;
    int nact = g_nact;

    for (int s = blockIdx.x; s < nact; s += gridDim.x) {
        int row = g_act[s];
        int b = row >> 11;
        int tt = g_tt[row];
        int j0 = (tt - 1) * M_MEDIA;

        qs[tid] = g_qact[(size_t)s * DIM + hg * 256 + tid];
        __syncthreads();

        // ---- qk: 4096 entries (h,c), 16 per thread, 64-wide float4 dots ----
        #pragma unroll
        for (int e = tid; e < 4 * DIM; e += 256) {
            int h = e >> 10, c = e & (DIM - 1);
            const float* wk = Wkv + (size_t)c * (2 * DIM) + hg * 256 + h * 64;
            const float* qh = qs + h * 64;
            float acc = 0.0f;
            #pragma unroll
            for (int d = 0; d < 64; d += 4) {
                float4 wv = *(const float4*)(wk + d);
                acc += wv.x * qh[d]     + wv.y * qh[d + 1]
                     + wv.z * qh[d + 2] + wv.w * qh[d + 3];
            }
            qkw[h][c] = acc;
        }
        __syncthreads();

        // ---- scores: warp per j (32 j each); coalesced c = u*32+lane ----
        {
            const float scale = 0.125f;
            for (int j = w8; j < M_MEDIA; j += 8) {
                const float* irow = image + ((size_t)(b * TM_TOT + j0 + j)) * DIM;
                float p0 = 0.f, p1 = 0.f, p2 = 0.f, p3 = 0.f;
                #pragma unroll 8
                for (int u = 0; u < 32; u++) {
                    int c = u * 32 + lane;
                    float iv = irow[c];
                    p0 = fmaf(iv, qkw[0][c], p0);
                    p1 = fmaf(iv, qkw[1][c], p1);
                    p2 = fmaf(iv, qkw[2][c], p2);
                    p3 = fmaf(iv, qkw[3][c], p3);
                }
                #pragma unroll
                for (int o = 16; o; o >>= 1) {
                    p0 += __shfl_xor_sync(0xffffffffu, p0, o);
                    p1 += __shfl_xor_sync(0xffffffffu, p1, o);
                    p2 += __shfl_xor_sync(0xffffffffu, p2, o);
                    p3 += __shfl_xor_sync(0xffffffffu, p3, o);
                }
                if (lane == 0) {
                    S[0][j] = p0 * scale; S[1][j] = p1 * scale;
                    S[2][j] = p2 * scale; S[3][j] = p3 * scale;
                }
            }
        }
        __syncthreads();

        // ---- softmax: warps 0..3, one local head each ----
        if (w8 < 4) {
            float vals[8];
            float m = -1e30f;
            #pragma unroll
            for (int k = 0; k < 8; k++) {
                vals[k] = S[w8][lane + 32 * k];
                m = fmaxf(m, vals[k]);
            }
            #pragma unroll
            for (int o = 16; o; o >>= 1) m = fmaxf(m, __shfl_xor_sync(0xffffffffu, m, o));
            float sum = 0.0f;
            #pragma unroll
            for (int k = 0; k < 8; k++) { vals[k] = __expf(vals[k] - m); sum += vals[k]; }
            #pragma unroll
            for (int o = 16; o; o >>= 1) sum += __shfl_xor_sync(0xffffffffu, sum, o);
            float inv = 1.0f / sum;
            #pragma unroll
            for (int k = 0; k < 8; k++) S[w8][lane + 32 * k] = vals[k] * inv;
        }
        __syncthreads();

        // ---- w[h][c] = sum_j p[h][j]*img[j][c]; thread owns 4 c; coalesced ----
        {
            int c0 = tid * 4;
            float acc[4][4];
            #pragma unroll
            for (int h = 0; h < 4; h++)
                #pragma unroll
                for (int u = 0; u < 4; u++) acc[h][u] = 0.0f;
            const float* ibase = image + ((size_t)(b * TM_TOT + j0)) * DIM + c0;
            #pragma unroll 4
            for (int j = 0; j < M_MEDIA; j++) {
                float4 iv = *(const float4*)(ibase + (size_t)j * DIM);
                #pragma unroll
                for (int h = 0; h < 4; h++) {
                    float p = S[h][j];
                    acc[h][0] = fmaf(p, iv.x, acc[h][0]);
                    acc[h][1] = fmaf(p, iv.y, acc[h][1]);
                    acc[h][2] = fmaf(p, iv.z, acc[h][2]);
                    acc[h][3] = fmaf(p, iv.w, acc[h][3]);
                }
            }
            __syncthreads();   // all qk reads done before overwrite
            #pragma unroll
            for (int h = 0; h < 4; h++) {
                qkw[h][c0 + 0] = acc[h][0];
                qkw[h][c0 + 1] = acc[h][1];
                qkw[h][c0 + 2] = acc[h][2];
                qkw[h][c0 + 3] = acc[h][3];
            }
        }
        __syncthreads();

        // ---- o[n] = sum_c w[h][c]*Wv[c][n]; warp-split K, 4 chunks of 64 n ----
        #pragma unroll
        for (int nc = 0; nc < 4; nc++) {       // local head = nc
            int n = hg * 256 + nc * 64 + lane * 2;
            const float* Wp = Wkv + (size_t)(w8 * 128) * (2 * DIM) + DIM + n;
            const float* xp = &qkw[nc][w8 * 128];
            float a0 = 0.0f, a1 = 0.0f;
            #pragma unroll 8
            for (int kk = 0; kk < 128; kk++) {
                float xv = xp[kk];
                float2 wv = *(const float2*)(Wp + (size_t)kk * (2 * DIM));
                a0 = fmaf(xv, wv.x, a0);
                a1 = fmaf(xv, wv.y, a1);
            }
            part[w8 * 64 + lane * 2]     = a0;
            part[w8 * 64 + lane * 2 + 1] = a1;
            __syncthreads();
            if (tid < 64) {
                float acc = 0.0f;
                #pragma unroll
                for (int ww = 0; ww < 8; ww++) acc += part[ww * 64 + tid];
                g_oact[(size_t)s * DIM + hg * 256 + nc * 64 + tid] = acc;
            }
            __syncthreads();
        }
    }
}

// ---------------------------------------------------------------------------
// Fill output: tt==0 -> 0, tt>4 -> omean, active rows skipped
// ---------------------------------------------------------------------------
__global__ void fill_kernel(float* __restrict__ out) {
    int row = blockIdx.x;
    int tt = g_tt[row];
    if (tt >= 1 && tt <= T_MEDIA) return;
    int tid = threadIdx.x;
    int b = row >> 11;
    float4 val = (tt == 0) ? make_float4(0.f, 0.f, 0.f, 0.f)
                           : ((const float4*)(g_omean + b * DIM))[tid];
    ((float4*)(out + (size_t)row * DIM))[tid] = val;
}

// ---------------------------------------------------------------------------
// out GEMV for active rows — parallel warp-split, grid (16, 64)
// ---------------------------------------------------------------------------
__global__ __launch_bounds__(256)
void out_act_kernel(const float* __restrict__ Wo, float* __restrict__ out) {
    __shared__ float x[DIM];
    __shared__ float part[8 * 64];
    int tid = threadIdx.x, lane = tid & 31, w = tid >> 5;
    int n0 = blockIdx.x * 64;
    int nact = g_nact;
    for (int s = blockIdx.y; s < nact; s += gridDim.y) {
        int row = g_act[s];
        ((float4*)x)[tid] = ((const float4*)(g_oact + (size_t)s * DIM))[tid];
        __syncthreads();
        gemv_chunk(Wo, DIM, x, part, n0, w, lane);
        __syncthreads();
        if (tid < 64) {
            float acc = 0.0f;
            #pragma unroll
            for (int ww = 0; ww < 8; ww++) acc += part[ww * 64 + tid];
            out[(size_t)row * DIM + n0 + tid] = acc;
        }
        __syncthreads();
    }
}

// ---------------------------------------------------------------------------
// Launch  (4th launch = attn_fused so ncu captures the new hot kernel)
// ---------------------------------------------------------------------------
extern "C" void kernel_launch(void* const* d_in, const int* in_sizes, int n_in,
                              void* d_out, int out_size) {
    const float* text  = (const float*)d_in[0];
    const float* image = (const float*)d_in[1];
    const int*   loc   = (const int*)d_in[2];
    const float* Wq    = (const float*)d_in[3];
    const float* Wkv   = (const float*)d_in[4];
    const float* Wo    = (const float*)d_in[5];
    const float* gamma = (const float*)d_in[6];
    const float* beta  = (const float*)d_in[7];
    float* out = (float*)d_out;

    // 1: txt_time scan (+ reset active counter)
    scan_kernel<<<BATCH, 1024>>>(loc);
    // 2: active row list
    compact_kernel<<<MQ / 1024, 1024>>>();
    // 3: fused LN + q GEMV for active rows
    qact_kernel<<<dim3(16, 64), 256>>>(text, gamma, beta, Wq);
    // 4: fused reassociated attention (profiled launch)
    attn_fused<<<dim3(64, 4), 256>>>(image, Wkv);
    // 5-6: image mean
    imgmean_part<<<dim3(DIM / 256, 32, BATCH), 256>>>(image);
    imgmean_final<<<dim3(DIM / 256, BATCH), 256>>>();
    // 7: vmean = imgmean @ Wv
    vmean_kernel<<<dim3(16, BATCH), 256>>>(Wkv);
    // 8: omean = vmean @ Wo
    omean_kernel<<<dim3(16, BATCH), 256>>>(Wo);
    // 9: fill inactive rows
    fill_kernel<<<MQ, 256>>>(out);
    // 10: out GEMV for active rows
    out_act_kernel<<<dim3(16, 64), 256>>>(Wo, out);
}

// round 10
// speedup vs baseline: 1.3714x; 1.3714x over previous
#include <cuda_runtime.h>
#include <cuda_bf16.h>
#include <math.h>
#include <stdint.h>

// Problem constants
#define BATCH   2
#define NTXT    2048
#define T_MEDIA 4
#define M_MEDIA 256
#define TM_TOT  1024
#define DIM     1024
#define HEADS   16
#define DH      64
#define EPS     1e-5f

#define MQ  (BATCH * NTXT)     // 4096
#define MKV (BATCH * TM_TOT)   // 2048

// ---------------------------------------------------------------------------
// Scratch (device globals; no allocations allowed)
// ---------------------------------------------------------------------------
__device__ __nv_bfloat16 g_img_hi[MKV * DIM];
__device__ __nv_bfloat16 g_img_lo[MKV * DIM];
__device__ __nv_bfloat16 g_Wkv_hi[2 * DIM * DIM];
__device__ __nv_bfloat16 g_Wkv_lo[2 * DIM * DIM];

__device__ float g_kv   [MKV * 2 * DIM];           // k | v (fp32)
__device__ float g_vpart[BATCH * 32 * DIM];
__device__ float g_vmean[BATCH * DIM];
__device__ float g_omean[BATCH * DIM];             // vmean @ Wo (fp32)
__device__ int   g_tt   [MQ];                      // txt_time
__device__ int   g_act  [MQ];                      // active rows (tt in [1..4])
__device__ int   g_nact;
__device__ float g_qact [MQ * DIM];                // q rows for active queries
__device__ float g_oact [MQ * DIM];                // attention out for active queries

// ---------------------------------------------------------------------------
// PTX helpers (sm_80-baseline only; NO tcgen05 — ptxas target lacks 'a')
// ---------------------------------------------------------------------------
__device__ __forceinline__ uint32_t smem_u32(const void* p) {
    uint32_t a;
    asm("{ .reg .u64 t; cvta.to.shared.u64 t, %1; cvt.u32.u64 %0, t; }" : "=r"(a) : "l"(p));
    return a;
}
__device__ __forceinline__ void cp_async16(uint32_t dst, const void* src) {
    asm volatile("cp.async.cg.shared.global [%0], [%1], 16;\n" :: "r"(dst), "l"(src));
}
__device__ __forceinline__ void ldsm4(uint32_t* r, uint32_t addr) {
    asm volatile("ldmatrix.sync.aligned.m8n8.x4.shared.b16 {%0,%1,%2,%3}, [%4];"
                 : "=r"(r[0]), "=r"(r[1]), "=r"(r[2]), "=r"(r[3]) : "r"(addr));
}
__device__ __forceinline__ void mma16816(float* c, const uint32_t* a,
                                         uint32_t b0, uint32_t b1) {
    asm volatile(
        "mma.sync.aligned.m16n8k16.row.col.f32.bf16.bf16.f32 "
        "{%0,%1,%2,%3}, {%4,%5,%6,%7}, {%8,%9}, {%0,%1,%2,%3};"
        : "+f"(c[0]), "+f"(c[1]), "+f"(c[2]), "+f"(c[3])
        : "r"(a[0]), "r"(a[1]), "r"(a[2]), "r"(a[3]), "r"(b0), "r"(b1));
}
__device__ __forceinline__ uint32_t sw128(uint32_t off) {
    return off ^ ((off >> 3) & 0x70);
}
__device__ __forceinline__ void split2(float v, __nv_bfloat16& h, __nv_bfloat16& l) {
    h = __float2bfloat16(v);
    l = __float2bfloat16(v - __bfloat162float(h));
}

// ---------------------------------------------------------------------------
// Warp-split GEMV core: y[n0..n0+64) = x[0..1024) @ W[.,n0..n0+64)
// ---------------------------------------------------------------------------
__device__ __forceinline__ void gemv_chunk(const float* __restrict__ W, int ldw,
                                           const float* __restrict__ x,
                                           float* __restrict__ part,
                                           int n0, int w, int lane) {
    float a0 = 0.0f, a1 = 0.0f;
    int n = n0 + lane * 2;
    const float* Wp = W + (size_t)(w * 128) * ldw + n;
    const float* xp = x + w * 128;
    #pragma unroll 8
    for (int kk = 0; kk < 128; kk++) {
        float xv = xp[kk];
        float2 wv = *(const float2*)(Wp + (size_t)kk * ldw);
        a0 = fmaf(xv, wv.x, a0);
        a1 = fmaf(xv, wv.y, a1);
    }
    part[w * 64 + lane * 2]     = a0;
    part[w * 64 + lane * 2 + 1] = a1;
}

// ---------------------------------------------------------------------------
// Inclusive scan of locations -> txt_time. One block of 1024 per batch.
// ---------------------------------------------------------------------------
__global__ void scan_kernel(const int* __restrict__ loc) {
    int b = blockIdx.x;
    int tid = threadIdx.x;
    if (b == 0 && tid == 0) g_nact = 0;
    __shared__ int s[1024];
    const int* L = loc + b * NTXT;
    int a0 = L[2 * tid];
    int a1 = L[2 * tid + 1];
    int v0 = a0, v1 = a0 + a1;
    s[tid] = v1;
    __syncthreads();
    for (int off = 1; off < 1024; off <<= 1) {
        int t = (tid >= off) ? s[tid - off] : 0;
        __syncthreads();
        s[tid] += t;
        __syncthreads();
    }
    int excl = s[tid] - v1;
    g_tt[b * NTXT + 2 * tid]     = excl + v0;
    g_tt[b * NTXT + 2 * tid + 1] = excl + v1;
}

__global__ void compact_kernel() {
    int row = blockIdx.x * 1024 + threadIdx.x;
    int tt = g_tt[row];
    if (tt >= 1 && tt <= T_MEDIA) {
        int slot = atomicAdd(&g_nact, 1);
        g_act[slot] = row;
    }
}

// ---------------------------------------------------------------------------
// Block reduce helper (256 threads)
// ---------------------------------------------------------------------------
__device__ __forceinline__ float blockReduceSum256(float v, float* red) {
    #pragma unroll
    for (int o = 16; o; o >>= 1) v += __shfl_xor_sync(0xffffffffu, v, o);
    int lane = threadIdx.x & 31, w = threadIdx.x >> 5;
    if (lane == 0) red[w] = v;
    __syncthreads();
    float r = (threadIdx.x < 8) ? red[threadIdx.x] : 0.0f;
    if (threadIdx.x < 32) {
        #pragma unroll
        for (int o = 4; o; o >>= 1) r += __shfl_xor_sync(0xffffffffu, r, o);
        if (threadIdx.x == 0) red[0] = r;
    }
    __syncthreads();
    float out = red[0];
    __syncthreads();
    return out;
}

// ---------------------------------------------------------------------------
// image fp32 -> hi/lo bf16 (elementwise)
// ---------------------------------------------------------------------------
__global__ void conv_img(const float* __restrict__ img) {
    size_t i = ((size_t)blockIdx.x * 256 + threadIdx.x) * 4;
    float4 v = *(const float4*)(img + i);
    __nv_bfloat16 h[4], l[4];
    split2(v.x, h[0], l[0]); split2(v.y, h[1], l[1]);
    split2(v.z, h[2], l[2]); split2(v.w, h[3], l[3]);
    *(__nv_bfloat162*)(g_img_hi + i)     = __nv_bfloat162(h[0], h[1]);
    *(__nv_bfloat162*)(g_img_hi + i + 2) = __nv_bfloat162(h[2], h[3]);
    *(__nv_bfloat162*)(g_img_lo + i)     = __nv_bfloat162(l[0], l[1]);
    *(__nv_bfloat162*)(g_img_lo + i + 2) = __nv_bfloat162(l[2], l[3]);
}

// ---------------------------------------------------------------------------
// Wkv [K,N] fp32 -> W^T [N,K] hi/lo bf16 (tiled transpose)
// ---------------------------------------------------------------------------
__global__ void wtrans(const float* __restrict__ W,
                       __nv_bfloat16* __restrict__ Thi,
                       __nv_bfloat16* __restrict__ Tlo,
                       int Kd, int Nd) {
    __shared__ float t[32][33];
    int bx = blockIdx.x * 32;
    int by = blockIdx.y * 32;
    int x = threadIdx.x & 31, y4 = (threadIdx.x >> 5) * 4;
    #pragma unroll
    for (int i = 0; i < 4; i++)
        t[y4 + i][x] = W[(size_t)(by + y4 + i) * Nd + bx + x];
    __syncthreads();
    #pragma unroll
    for (int i = 0; i < 4; i++) {
        float v = t[x][y4 + i];
        __nv_bfloat16 h, l;
        split2(v, h, l);
        size_t o = (size_t)(bx + y4 + i) * Kd + by + x;
        Thi[o] = h;
        Tlo[o] = l;
    }
}

// ---------------------------------------------------------------------------
// bf16 split GEMM via mma.sync (HMMA), 3-stage cp.async pipeline.
// C[M,N] = A[M,K] @ B^T (B stored [N,K]); K' = 3K split.
// ---------------------------------------------------------------------------
#define GBM 128
#define GBN 128
#define GBK 64
#define KTILES 48
#define ABYTES (GBM * GBK * 2)                // 16384
#define BBYTES (GBN * GBK * 2)                // 16384
#define STG    3
#define SMEM_GEMM (STG * (ABYTES + BBYTES))   // 98304

__global__ __launch_bounds__(256, 2)
void gemm_hmma_split(const __nv_bfloat16* __restrict__ A_hi,
                     const __nv_bfloat16* __restrict__ A_lo,
                     const __nv_bfloat16* __restrict__ B_hi,
                     const __nv_bfloat16* __restrict__ B_lo,
                     float* __restrict__ C, int N) {
    extern __shared__ char smem[];
    const int K = 1024;
    uint32_t sb = smem_u32(smem);
    int tid = threadIdx.x;
    int lane = tid & 31, wid = tid >> 5;
    int row0 = blockIdx.y * GBM, col0 = blockIdx.x * GBN;

    int lr = tid >> 3;
    int lc = tid & 7;

    int wm = wid >> 2, wn = wid & 3;
    int m_warp = wm * 64, n_warp = wn * 32;
    int a_row = lane & 15;
    int a_colb = (lane >> 4) * 8;
    int b_row = (lane & 7) + 8 * ((lane >> 4) & 1);
    int b_colb = 8 * ((lane >> 3) & 1);

    float acc[4][4][4];
    #pragma unroll
    for (int i = 0; i < 4; i++)
        #pragma unroll
        for (int j = 0; j < 4; j++)
            #pragma unroll
            for (int q = 0; q < 4; q++) acc[i][j][q] = 0.0f;

    auto issue = [&](int kt) {
        int term = kt >> 4;
        int ks = (kt & 15) * GBK;
        uint32_t abase = sb + (uint32_t)((kt % STG) * (ABYTES + BBYTES));
        uint32_t bbase = abase + ABYTES;
        const __nv_bfloat16* Ag = (term < 2) ? A_hi : A_lo;
        const __nv_bfloat16* Bg = (term == 1) ? B_lo : B_hi;
        #pragma unroll
        for (int j = 0; j < 4; j++) {
            int r = lr + 32 * j;
            uint32_t off = (uint32_t)(r * 128 + lc * 16);
            cp_async16(abase + sw128(off),
                       Ag + (size_t)(row0 + r) * K + ks + lc * 8);
        }
        #pragma unroll
        for (int j = 0; j < 4; j++) {
            int r = lr + 32 * j;
            uint32_t off = (uint32_t)(r * 128 + lc * 16);
            cp_async16(bbase + sw128(off),
                       Bg + (size_t)(col0 + r) * K + ks + lc * 8);
        }
        asm volatile("cp.async.commit_group;" ::: "memory");
    };

    issue(0);
    issue(1);

    #pragma unroll 1
    for (int kt = 0; kt < KTILES; kt++) {
        if (kt + 2 < KTILES) {
            issue(kt + 2);
            asm volatile("cp.async.wait_group 2;" ::: "memory");
        } else if (kt + 1 < KTILES) {
            asm volatile("cp.async.wait_group 1;" ::: "memory");
        } else {
            asm volatile("cp.async.wait_group 0;" ::: "memory");
        }
        __syncthreads();

        uint32_t ab = sb + (uint32_t)((kt % STG) * (ABYTES + BBYTES));
        uint32_t bb = ab + ABYTES;
        #pragma unroll
        for (int k16 = 0; k16 < 4; k16++) {
            uint32_t a_r[4][4], b_r[2][4];
            #pragma unroll
            for (int mf = 0; mf < 4; mf++) {
                uint32_t off = (uint32_t)((m_warp + mf * 16 + a_row) * 128 +
                                          (k16 * 16 + a_colb) * 2);
                ldsm4(a_r[mf], ab + sw128(off));
            }
            #pragma unroll
            for (int nf2 = 0; nf2 < 2; nf2++) {
                uint32_t off = (uint32_t)((n_warp + nf2 * 16 + b_row) * 128 +
                                          (k16 * 16 + b_colb) * 2);
                ldsm4(b_r[nf2], bb + sw128(off));
            }
            #pragma unroll
            for (int mf = 0; mf < 4; mf++)
                #pragma unroll
                for (int nf = 0; nf < 4; nf++) {
                    const uint32_t* b2 = &b_r[nf >> 1][(nf & 1) * 2];
                    mma16816(acc[mf][nf], a_r[mf], b2[0], b2[1]);
                }
        }
        __syncthreads();
    }

    int r_base = row0 + m_warp + (lane >> 2);
    int c_base = col0 + n_warp + 2 * (lane & 3);
    #pragma unroll
    for (int mf = 0; mf < 4; mf++)
        #pragma unroll
        for (int nf = 0; nf < 4; nf++) {
            float* p = C + (size_t)(r_base + mf * 16) * N + c_base + nf * 8;
            *(float2*)p = make_float2(acc[mf][nf][0], acc[mf][nf][1]);
            *(float2*)(p + (size_t)8 * N) = make_float2(acc[mf][nf][2], acc[mf][nf][3]);
        }
}

// ---------------------------------------------------------------------------
// v column partial sums + final mean
// ---------------------------------------------------------------------------
__global__ void vpart_kernel() {
    int c  = blockIdx.x * 256 + threadIdx.x;
    int ry = blockIdx.y;
    int b  = blockIdx.z;
    const float* base = g_kv + ((size_t)(b * TM_TOT + ry * 32)) * (2 * DIM) + DIM + c;
    float s = 0.0f;
    #pragma unroll 8
    for (int j = 0; j < 32; j++) s += base[(size_t)j * (2 * DIM)];
    g_vpart[(b * 32 + ry) * DIM + c] = s;
}

__global__ void vmean_kernel() {
    int c = blockIdx.x * 256 + threadIdx.x;
    int b = blockIdx.y;
    float s = 0.0f;
    #pragma unroll
    for (int r = 0; r < 32; r++) s += g_vpart[(b * 32 + r) * DIM + c];
    g_vmean[b * DIM + c] = s * (1.0f / TM_TOT);
}

// omean[b] = vmean[b] @ Wo  — parallel warp-split GEMV, grid (16, BATCH)
__global__ __launch_bounds__(256)
void omean_kernel(const float* __restrict__ Wo) {
    __shared__ float x[DIM];
    __shared__ float part[8 * 64];
    int tid = threadIdx.x, lane = tid & 31, w = tid >> 5;
    int n0 = blockIdx.x * 64;
    int b = blockIdx.y;
    ((float4*)x)[tid] = ((const float4*)(g_vmean + b * DIM))[tid];
    __syncthreads();
    gemv_chunk(Wo, DIM, x, part, n0, w, lane);
    __syncthreads();
    if (tid < 64) {
        float acc = 0.0f;
        #pragma unroll
        for (int ww = 0; ww < 8; ww++) acc += part[ww * 64 + tid];
        g_omean[b * DIM + n0 + tid] = acc;
    }
}

// ---------------------------------------------------------------------------
// Fused LayerNorm + q GEMV for active rows.  grid (16 n-chunks, 64 slots)
// ---------------------------------------------------------------------------
__global__ __launch_bounds__(256)
void qact_kernel(const float* __restrict__ text,
                 const float* __restrict__ gamma,
                 const float* __restrict__ beta,
                 const float* __restrict__ Wq) {
    __shared__ float x[DIM];
    __shared__ float red[8];
    __shared__ float part[8 * 64];
    int tid = threadIdx.x, lane = tid & 31, w = tid >> 5;
    int n0 = blockIdx.x * 64;
    int nact = g_nact;
    for (int s = blockIdx.y; s < nact; s += gridDim.y) {
        int row = g_act[s];
        float4 v = ((const float4*)(text + (size_t)row * DIM))[tid];
        float sm = v.x + v.y + v.z + v.w;
        float mu = blockReduceSum256(sm, red) * (1.0f / DIM);
        float dx = v.x - mu, dy = v.y - mu, dz = v.z - mu, dw = v.w - mu;
        float var = blockReduceSum256(dx * dx + dy * dy + dz * dz + dw * dw, red) * (1.0f / DIM);
        float inv = rsqrtf(var + EPS);
        float4 g = ((const float4*)gamma)[tid];
        float4 bt = ((const float4*)beta)[tid];
        x[4 * tid + 0] = dx * inv * g.x + bt.x;
        x[4 * tid + 1] = dy * inv * g.y + bt.y;
        x[4 * tid + 2] = dz * inv * g.z + bt.z;
        x[4 * tid + 3] = dw * inv * g.w + bt.w;
        __syncthreads();
        gemv_chunk(Wq, DIM, x, part, n0, w, lane);
        __syncthreads();
        if (tid < 64) {
            float acc = 0.0f;
            #pragma unroll
            for (int ww = 0; ww < 8; ww++) acc += part[ww * 64 + tid];
            g_qact[(size_t)s * DIM + n0 + tid] = acc;
        }
        __syncthreads();
    }
}

// ---------------------------------------------------------------------------
// Segment attention per (slot, head-group of 4 heads). grid (64, 4).
// ---------------------------------------------------------------------------
__global__ __launch_bounds__(256)
void attn_act_kernel() {
    __shared__ float qs[256];
    __shared__ float S[4][M_MEDIA];
    __shared__ float part[8][256];
    int tid = threadIdx.x;
    int lane = tid & 31, w = tid >> 5;
    int hg = blockIdx.y;
    int nact = g_nact;

    for (int s = blockIdx.x; s < nact; s += gridDim.x) {
        int row = g_act[s];
        int b = row >> 11;
        int tt = g_tt[row];
        int j0 = (tt - 1) * M_MEDIA;

        qs[tid] = g_qact[(size_t)s * DIM + hg * 256 + tid];
        __syncthreads();

        // scores: warp w handles j in [32w, 32w+32); lane covers 8 c; head = lane>>3
        {
            const float scale = 0.125f;
            int c0 = lane * 8;
            int h = lane >> 3;
            const float* kbase = g_kv + ((size_t)(b * TM_TOT + j0 + w * 32)) * (2 * DIM)
                               + hg * 256 + c0;
            for (int jj = 0; jj < 32; jj++) {
                const float* krow = kbase + (size_t)jj * (2 * DIM);
                float4 k0 = *(const float4*)(krow);
                float4 k1 = *(const float4*)(krow + 4);
                float p = k0.x * qs[c0]     + k0.y * qs[c0 + 1] +
                          k0.z * qs[c0 + 2] + k0.w * qs[c0 + 3] +
                          k1.x * qs[c0 + 4] + k1.y * qs[c0 + 5] +
                          k1.z * qs[c0 + 6] + k1.w * qs[c0 + 7];
                p += __shfl_xor_sync(0xffffffffu, p, 4);
                p += __shfl_xor_sync(0xffffffffu, p, 2);
                p += __shfl_xor_sync(0xffffffffu, p, 1);
                if ((lane & 7) == 0) S[h][w * 32 + jj] = p * scale;
            }
        }
        __syncthreads();

        // softmax: warp 0..3 per local head
        if (w < 4) {
            float vals[8];
            float m = -1e30f;
            #pragma unroll
            for (int k = 0; k < 8; k++) {
                vals[k] = S[w][lane + 32 * k];
                m = fmaxf(m, vals[k]);
            }
            #pragma unroll
            for (int o = 16; o; o >>= 1) m = fmaxf(m, __shfl_xor_sync(0xffffffffu, m, o));
            float sum = 0.0f;
            #pragma unroll
            for (int k = 0; k < 8; k++) { vals[k] = __expf(vals[k] - m); sum += vals[k]; }
            #pragma unroll
            for (int o = 16; o; o >>= 1) sum += __shfl_xor_sync(0xffffffffu, sum, o);
            float inv = 1.0f / sum;
            #pragma unroll
            for (int k = 0; k < 8; k++) S[w][lane + 32 * k] = vals[k] * inv;
        }
        __syncthreads();

        // AV: warp w handles j in [32w, 32w+32); lane covers 8 n; head = lane>>3
        {
            int c0 = lane * 8;
            int h = lane >> 3;
            float acc[8] = {0, 0, 0, 0, 0, 0, 0, 0};
            const float* vbase = g_kv + ((size_t)(b * TM_TOT + j0 + w * 32)) * (2 * DIM)
                               + DIM + hg * 256 + c0;
            #pragma unroll 4
            for (int jj = 0; jj < 32; jj++) {
                float p = S[h][w * 32 + jj];
                const float* vr = vbase + (size_t)jj * (2 * DIM);
                float4 v0 = *(const float4*)(vr);
                float4 v1 = *(const float4*)(vr + 4);
                acc[0] = fmaf(p, v0.x, acc[0]); acc[1] = fmaf(p, v0.y, acc[1]);
                acc[2] = fmaf(p, v0.z, acc[2]); acc[3] = fmaf(p, v0.w, acc[3]);
                acc[4] = fmaf(p, v1.x, acc[4]); acc[5] = fmaf(p, v1.y, acc[5]);
                acc[6] = fmaf(p, v1.z, acc[6]); acc[7] = fmaf(p, v1.w, acc[7]);
            }
            #pragma unroll
            for (int u = 0; u < 8; u++) part[w][c0 + u] = acc[u];
        }
        __syncthreads();

        {
            float a = 0.0f;
            #pragma unroll
            for (int ww = 0; ww < 8; ww++) a += part[ww][tid];
            g_oact[(size_t)s * DIM + hg * 256 + tid] = a;
        }
        __syncthreads();
    }
}

// ---------------------------------------------------------------------------
// Fill output: tt==0 -> 0, tt>4 -> omean, active rows skipped
// ---------------------------------------------------------------------------
__global__ void fill_kernel(float* __restrict__ out) {
    int row = blockIdx.x;
    int tt = g_tt[row];
    if (tt >= 1 && tt <= T_MEDIA) return;
    int tid = threadIdx.x;
    int b = row >> 11;
    float4 val = (tt == 0) ? make_float4(0.f, 0.f, 0.f, 0.f)
                           : ((const float4*)(g_omean + b * DIM))[tid];
    ((float4*)(out + (size_t)row * DIM))[tid] = val;
}

// ---------------------------------------------------------------------------
// out GEMV for active rows — parallel warp-split, grid (16, 64)
// ---------------------------------------------------------------------------
__global__ __launch_bounds__(256)
void out_act_kernel(const float* __restrict__ Wo, float* __restrict__ out) {
    __shared__ float x[DIM];
    __shared__ float part[8 * 64];
    int tid = threadIdx.x, lane = tid & 31, w = tid >> 5;
    int n0 = blockIdx.x * 64;
    int nact = g_nact;
    for (int s = blockIdx.y; s < nact; s += gridDim.y) {
        int row = g_act[s];
        ((float4*)x)[tid] = ((const float4*)(g_oact + (size_t)s * DIM))[tid];
        __syncthreads();
        gemv_chunk(Wo, DIM, x, part, n0, w, lane);
        __syncthreads();
        if (tid < 64) {
            float acc = 0.0f;
            #pragma unroll
            for (int ww = 0; ww < 8; ww++) acc += part[ww * 64 + tid];
            out[(size_t)row * DIM + n0 + tid] = acc;
        }
        __syncthreads();
    }
}

// ---------------------------------------------------------------------------
// Launch — two-stream fork/join: q-branch overlaps the kv GEMM branch.
// Streams/events created once on the (uncaptured) correctness call.
// 4th launch on main stream = kv GEMM (profiled).
// ---------------------------------------------------------------------------
extern "C" void kernel_launch(void* const* d_in, const int* in_sizes, int n_in,
                              void* d_out, int out_size) {
    const float* text  = (const float*)d_in[0];
    const float* image = (const float*)d_in[1];
    const int*   loc   = (const int*)d_in[2];
    const float* Wq    = (const float*)d_in[3];
    const float* Wkv   = (const float*)d_in[4];
    const float* Wo    = (const float*)d_in[5];
    const float* gamma = (const float*)d_in[6];
    const float* beta  = (const float*)d_in[7];
    float* out = (float*)d_out;

    static cudaStream_t s2 = nullptr;
    static cudaEvent_t evFork = nullptr, evJoin = nullptr;
    static int inited = 0;
    if (!inited) {
        cudaFuncSetAttribute(gemm_hmma_split,
                             cudaFuncAttributeMaxDynamicSharedMemorySize, SMEM_GEMM);
        cudaStreamCreateWithFlags(&s2, cudaStreamNonBlocking);
        cudaEventCreateWithFlags(&evFork, cudaEventDisableTiming);
        cudaEventCreateWithFlags(&evJoin, cudaEventDisableTiming);
        inited = 1;
    }

    __nv_bfloat16 *img_hi, *img_lo, *wkv_hi, *wkv_lo;
    float *p_kv;
    cudaGetSymbolAddress((void**)&img_hi, g_img_hi);
    cudaGetSymbolAddress((void**)&img_lo, g_img_lo);
    cudaGetSymbolAddress((void**)&wkv_hi, g_Wkv_hi);
    cudaGetSymbolAddress((void**)&wkv_lo, g_Wkv_lo);
    cudaGetSymbolAddress((void**)&p_kv,   g_kv);

    // Fork: q-branch on s2 (scan -> compact -> qact), independent of kv branch.
    cudaEventRecord(evFork, 0);
    cudaStreamWaitEvent(s2, evFork, 0);
    scan_kernel<<<BATCH, 1024, 0, s2>>>(loc);
    compact_kernel<<<MQ / 1024, 1024, 0, s2>>>();
    qact_kernel<<<dim3(16, 64), 256, 0, s2>>>(text, gamma, beta, Wq);
    cudaEventRecord(evJoin, s2);

    // kv branch on main stream
    conv_img<<<(MKV * DIM) / (256 * 4), 256>>>(image);
    wtrans<<<dim3(2 * DIM / 32, DIM / 32), 256>>>(Wkv, wkv_hi, wkv_lo, DIM, 2 * DIM);
    gemm_hmma_split<<<dim3(2 * DIM / GBN, MKV / GBM), 256, SMEM_GEMM>>>(
        img_hi, img_lo, wkv_hi, wkv_lo, p_kv, 2 * DIM);
    vpart_kernel<<<dim3(DIM / 256, 32, BATCH), 256>>>();
    vmean_kernel<<<dim3(DIM / 256, BATCH), 256>>>();
    omean_kernel<<<dim3(16, BATCH), 256>>>(Wo);

    // Join, then the kv+q dependent tail
    cudaStreamWaitEvent(0, evJoin, 0);
    attn_act_kernel<<<dim3(64, 4), 256>>>();
    fill_kernel<<<MQ, 256>>>(out);
    out_act_kernel<<<dim3(16, 64), 256>>>(Wo, out);
}

// round 11
// speedup vs baseline: 1.6494x; 1.2027x over previous
#include <cuda_runtime.h>
#include <cuda_bf16.h>
#include <math.h>
#include <stdint.h>

// Problem constants
#define BATCH   2
#define NTXT    2048
#define T_MEDIA 4
#define M_MEDIA 256
#define TM_TOT  1024
#define DIM     1024
#define HEADS   16
#define DH      64
#define EPS     1e-5f

#define MQ  (BATCH * NTXT)     // 4096
#define MKV (BATCH * TM_TOT)   // 2048

// ---------------------------------------------------------------------------
// Scratch (device globals; no allocations allowed)
// ---------------------------------------------------------------------------
__device__ __nv_bfloat16 g_img_hi[MKV * DIM];
__device__ __nv_bfloat16 g_img_lo[MKV * DIM];
__device__ __nv_bfloat16 g_Wkv_hi[2 * DIM * DIM];
__device__ __nv_bfloat16 g_Wkv_lo[2 * DIM * DIM];

__device__ float g_kv   [MKV * 2 * DIM];           // k | v (fp32)
__device__ float g_vmean[BATCH * DIM];             // SUM of v cols (scaled later)
__device__ float g_omean[BATCH * DIM];             // (vmean/1024) @ Wo (fp32)
__device__ int   g_tt   [MQ];                      // txt_time
__device__ int   g_act  [MQ];                      // active rows (tt in [1..4])
__device__ int   g_nact;
__device__ float g_qact [MQ * DIM];                // q rows for active queries
__device__ float g_oact [MQ * DIM];                // attention out for active queries

// ---------------------------------------------------------------------------
// PTX helpers (sm_80-baseline only; NO tcgen05 — ptxas target lacks 'a')
// ---------------------------------------------------------------------------
__device__ __forceinline__ uint32_t smem_u32(const void* p) {
    uint32_t a;
    asm("{ .reg .u64 t; cvta.to.shared.u64 t, %1; cvt.u32.u64 %0, t; }" : "=r"(a) : "l"(p));
    return a;
}
__device__ __forceinline__ void cp_async16(uint32_t dst, const void* src) {
    asm volatile("cp.async.cg.shared.global [%0], [%1], 16;\n" :: "r"(dst), "l"(src));
}
__device__ __forceinline__ void ldsm4(uint32_t* r, uint32_t addr) {
    asm volatile("ldmatrix.sync.aligned.m8n8.x4.shared.b16 {%0,%1,%2,%3}, [%4];"
                 : "=r"(r[0]), "=r"(r[1]), "=r"(r[2]), "=r"(r[3]) : "r"(addr));
}
__device__ __forceinline__ void mma16816(float* c, const uint32_t* a,
                                         uint32_t b0, uint32_t b1) {
    asm volatile(
        "mma.sync.aligned.m16n8k16.row.col.f32.bf16.bf16.f32 "
        "{%0,%1,%2,%3}, {%4,%5,%6,%7}, {%8,%9}, {%0,%1,%2,%3};"
        : "+f"(c[0]), "+f"(c[1]), "+f"(c[2]), "+f"(c[3])
        : "r"(a[0]), "r"(a[1]), "r"(a[2]), "r"(a[3]), "r"(b0), "r"(b1));
}
__device__ __forceinline__ uint32_t sw128(uint32_t off) {
    return off ^ ((off >> 3) & 0x70);
}
__device__ __forceinline__ void split2(float v, __nv_bfloat16& h, __nv_bfloat16& l) {
    h = __float2bfloat16(v);
    l = __float2bfloat16(v - __bfloat162float(h));
}

// ---------------------------------------------------------------------------
// Warp-split GEMV core: y[n0..n0+64) = x[0..1024) @ W[.,n0..n0+64)
// ---------------------------------------------------------------------------
__device__ __forceinline__ void gemv_chunk(const float* __restrict__ W, int ldw,
                                           const float* __restrict__ x,
                                           float* __restrict__ part,
                                           int n0, int w, int lane) {
    float a0 = 0.0f, a1 = 0.0f;
    int n = n0 + lane * 2;
    const float* Wp = W + (size_t)(w * 128) * ldw + n;
    const float* xp = x + w * 128;
    #pragma unroll 8
    for (int kk = 0; kk < 128; kk++) {
        float xv = xp[kk];
        float2 wv = *(const float2*)(Wp + (size_t)kk * ldw);
        a0 = fmaf(xv, wv.x, a0);
        a1 = fmaf(xv, wv.y, a1);
    }
    part[w * 64 + lane * 2]     = a0;
    part[w * 64 + lane * 2 + 1] = a1;
}

// ---------------------------------------------------------------------------
// Inclusive scan of locations -> txt_time. One block of 1024 per batch.
// ---------------------------------------------------------------------------
__global__ void scan_kernel(const int* __restrict__ loc) {
    int b = blockIdx.x;
    int tid = threadIdx.x;
    if (b == 0 && tid == 0) g_nact = 0;
    __shared__ int s[1024];
    const int* L = loc + b * NTXT;
    int a0 = L[2 * tid];
    int a1 = L[2 * tid + 1];
    int v0 = a0, v1 = a0 + a1;
    s[tid] = v1;
    __syncthreads();
    for (int off = 1; off < 1024; off <<= 1) {
        int t = (tid >= off) ? s[tid - off] : 0;
        __syncthreads();
        s[tid] += t;
        __syncthreads();
    }
    int excl = s[tid] - v1;
    g_tt[b * NTXT + 2 * tid]     = excl + v0;
    g_tt[b * NTXT + 2 * tid + 1] = excl + v1;
}

__global__ void compact_kernel() {
    int row = blockIdx.x * 1024 + threadIdx.x;
    int tt = g_tt[row];
    if (tt >= 1 && tt <= T_MEDIA) {
        int slot = atomicAdd(&g_nact, 1);
        g_act[slot] = row;
    }
}

// ---------------------------------------------------------------------------
// Block reduce helper (256 threads)
// ---------------------------------------------------------------------------
__device__ __forceinline__ float blockReduceSum256(float v, float* red) {
    #pragma unroll
    for (int o = 16; o; o >>= 1) v += __shfl_xor_sync(0xffffffffu, v, o);
    int lane = threadIdx.x & 31, w = threadIdx.x >> 5;
    if (lane == 0) red[w] = v;
    __syncthreads();
    float r = (threadIdx.x < 8) ? red[threadIdx.x] : 0.0f;
    if (threadIdx.x < 32) {
        #pragma unroll
        for (int o = 4; o; o >>= 1) r += __shfl_xor_sync(0xffffffffu, r, o);
        if (threadIdx.x == 0) red[0] = r;
    }
    __syncthreads();
    float out = red[0];
    __syncthreads();
    return out;
}

// ---------------------------------------------------------------------------
// image fp32 -> hi/lo bf16 (elementwise).  Also zeroes g_vmean (blocks 0..7),
// which runs before the GEMM's epilogue atomics on the same stream.
// ---------------------------------------------------------------------------
__global__ void conv_img(const float* __restrict__ img) {
    if (blockIdx.x < 8) g_vmean[blockIdx.x * 256 + threadIdx.x] = 0.0f;
    size_t i = ((size_t)blockIdx.x * 256 + threadIdx.x) * 4;
    float4 v = *(const float4*)(img + i);
    __nv_bfloat16 h[4], l[4];
    split2(v.x, h[0], l[0]); split2(v.y, h[1], l[1]);
    split2(v.z, h[2], l[2]); split2(v.w, h[3], l[3]);
    *(__nv_bfloat162*)(g_img_hi + i)     = __nv_bfloat162(h[0], h[1]);
    *(__nv_bfloat162*)(g_img_hi + i + 2) = __nv_bfloat162(h[2], h[3]);
    *(__nv_bfloat162*)(g_img_lo + i)     = __nv_bfloat162(l[0], l[1]);
    *(__nv_bfloat162*)(g_img_lo + i + 2) = __nv_bfloat162(l[2], l[3]);
}

// ---------------------------------------------------------------------------
// Wkv [K,N] fp32 -> W^T [N,K] hi/lo bf16 (tiled transpose)
// ---------------------------------------------------------------------------
__global__ void wtrans(const float* __restrict__ W,
                       __nv_bfloat16* __restrict__ Thi,
                       __nv_bfloat16* __restrict__ Tlo,
                       int Kd, int Nd) {
    __shared__ float t[32][33];
    int bx = blockIdx.x * 32;
    int by = blockIdx.y * 32;
    int x = threadIdx.x & 31, y4 = (threadIdx.x >> 5) * 4;
    #pragma unroll
    for (int i = 0; i < 4; i++)
        t[y4 + i][x] = W[(size_t)(by + y4 + i) * Nd + bx + x];
    __syncthreads();
    #pragma unroll
    for (int i = 0; i < 4; i++) {
        float v = t[x][y4 + i];
        __nv_bfloat16 h, l;
        split2(v, h, l);
        size_t o = (size_t)(bx + y4 + i) * Kd + by + x;
        Thi[o] = h;
        Tlo[o] = l;
    }
}

// ---------------------------------------------------------------------------
// bf16 split GEMM via mma.sync (HMMA), 3-stage cp.async pipeline.
// CTA tile 128x256, 8 warps at 64x64 each.  K' = 3K split.
// v-half CTAs (col0 >= DIM) accumulate column sums into g_vmean (atomics).
// ---------------------------------------------------------------------------
#define GBM 128
#define GBN 256
#define GBK 64
#define KTILES 48
#define ABYTES (GBM * GBK * 2)                // 16384
#define BBYTES (GBN * GBK * 2)                // 32768
#define STG    3
#define SMEM_GEMM (STG * (ABYTES + BBYTES))   // 147456

__global__ __launch_bounds__(256, 1)
void gemm_hmma_split(const __nv_bfloat16* __restrict__ A_hi,
                     const __nv_bfloat16* __restrict__ A_lo,
                     const __nv_bfloat16* __restrict__ B_hi,
                     const __nv_bfloat16* __restrict__ B_lo,
                     float* __restrict__ C, int N) {
    extern __shared__ char smem[];
    const int K = 1024;
    uint32_t sb = smem_u32(smem);
    int tid = threadIdx.x;
    int lane = tid & 31, wid = tid >> 5;
    int row0 = blockIdx.y * GBM, col0 = blockIdx.x * GBN;

    int lr = tid >> 3;            // 0..31
    int lc = tid & 7;             // 0..7 (16B chunk in 128B row)

    int wm = wid >> 2, wn = wid & 3;       // 2 x 4 warp grid
    int m_warp = wm * 64, n_warp = wn * 64;
    int a_row = lane & 15;
    int a_colb = (lane >> 4) * 8;
    int b_row = (lane & 7) + 8 * ((lane >> 4) & 1);
    int b_colb = 8 * ((lane >> 3) & 1);

    float acc[4][8][4];
    #pragma unroll
    for (int i = 0; i < 4; i++)
        #pragma unroll
        for (int j = 0; j < 8; j++)
            #pragma unroll
            for (int q = 0; q < 4; q++) acc[i][j][q] = 0.0f;

    auto issue = [&](int kt) {
        int term = kt >> 4;
        int ks = (kt & 15) * GBK;
        uint32_t abase = sb + (uint32_t)((kt % STG) * (ABYTES + BBYTES));
        uint32_t bbase = abase + ABYTES;
        const __nv_bfloat16* Ag = (term < 2) ? A_hi : A_lo;
        const __nv_bfloat16* Bg = (term == 1) ? B_lo : B_hi;
        #pragma unroll
        for (int j = 0; j < 4; j++) {
            int r = lr + 32 * j;
            uint32_t off = (uint32_t)(r * 128 + lc * 16);
            cp_async16(abase + sw128(off),
                       Ag + (size_t)(row0 + r) * K + ks + lc * 8);
        }
        #pragma unroll
        for (int j = 0; j < 8; j++) {
            int r = lr + 32 * j;
            uint32_t off = (uint32_t)(r * 128 + lc * 16);
            cp_async16(bbase + sw128(off),
                       Bg + (size_t)(col0 + r) * K + ks + lc * 8);
        }
        asm volatile("cp.async.commit_group;" ::: "memory");
    };

    issue(0);
    issue(1);

    #pragma unroll 1
    for (int kt = 0; kt < KTILES; kt++) {
        if (kt + 2 < KTILES) {
            issue(kt + 2);
            asm volatile("cp.async.wait_group 2;" ::: "memory");
        } else if (kt + 1 < KTILES) {
            asm volatile("cp.async.wait_group 1;" ::: "memory");
        } else {
            asm volatile("cp.async.wait_group 0;" ::: "memory");
        }
        __syncthreads();

        uint32_t ab = sb + (uint32_t)((kt % STG) * (ABYTES + BBYTES));
        uint32_t bb = ab + ABYTES;
        #pragma unroll
        for (int k16 = 0; k16 < 4; k16++) {
            uint32_t a_r[4][4], b_r[4][4];
            #pragma unroll
            for (int mf = 0; mf < 4; mf++) {
                uint32_t off = (uint32_t)((m_warp + mf * 16 + a_row) * 128 +
                                          (k16 * 16 + a_colb) * 2);
                ldsm4(a_r[mf], ab + sw128(off));
            }
            #pragma unroll
            for (int nf2 = 0; nf2 < 4; nf2++) {
                uint32_t off = (uint32_t)((n_warp + nf2 * 16 + b_row) * 128 +
                                          (k16 * 16 + b_colb) * 2);
                ldsm4(b_r[nf2], bb + sw128(off));
            }
            #pragma unroll
            for (int mf = 0; mf < 4; mf++)
                #pragma unroll
                for (int nf = 0; nf < 8; nf++) {
                    const uint32_t* b2 = &b_r[nf >> 1][(nf & 1) * 2];
                    mma16816(acc[mf][nf], a_r[mf], b2[0], b2[1]);
                }
        }
        __syncthreads();
    }

    // ---- epilogue: store C ----
    int r_base = row0 + m_warp + (lane >> 2);
    int c_base = col0 + n_warp + 2 * (lane & 3);
    #pragma unroll
    for (int mf = 0; mf < 4; mf++)
        #pragma unroll
        for (int nf = 0; nf < 8; nf++) {
            float* p = C + (size_t)(r_base + mf * 16) * N + c_base + nf * 8;
            *(float2*)p = make_float2(acc[mf][nf][0], acc[mf][nf][1]);
            *(float2*)(p + (size_t)8 * N) = make_float2(acc[mf][nf][2], acc[mf][nf][3]);
        }

    // ---- fused v column sums (only v half: col0 >= DIM) ----
    if (col0 >= DIM) {
        int b = row0 >> 10;
        #pragma unroll
        for (int nf = 0; nf < 8; nf++) {
            float c0s = 0.0f, c1s = 0.0f;
            #pragma unroll
            for (int mf = 0; mf < 4; mf++) {
                c0s += acc[mf][nf][0] + acc[mf][nf][2];
                c1s += acc[mf][nf][1] + acc[mf][nf][3];
            }
            // reduce across the 8 lanes sharing the same (lane & 3)
            #pragma unroll
            for (int o = 4; o <= 16; o <<= 1) {
                c0s += __shfl_xor_sync(0xffffffffu, c0s, o);
                c1s += __shfl_xor_sync(0xffffffffu, c1s, o);
            }
            if ((lane >> 2) == 0) {
                int c = c_base + nf * 8 - DIM;
                atomicAdd(&g_vmean[b * DIM + c], c0s);
                atomicAdd(&g_vmean[b * DIM + c + 1], c1s);
            }
        }
    }
}

// ---------------------------------------------------------------------------
// omean[b] = (vmean[b]/TM_TOT) @ Wo  — parallel warp-split GEMV, grid (16, BATCH)
// ---------------------------------------------------------------------------
__global__ __launch_bounds__(256)
void omean_kernel(const float* __restrict__ Wo) {
    __shared__ float x[DIM];
    __shared__ float part[8 * 64];
    int tid = threadIdx.x, lane = tid & 31, w = tid >> 5;
    int n0 = blockIdx.x * 64;
    int b = blockIdx.y;
    float4 v = ((const float4*)(g_vmean + b * DIM))[tid];
    const float sc = 1.0f / TM_TOT;
    x[4 * tid + 0] = v.x * sc; x[4 * tid + 1] = v.y * sc;
    x[4 * tid + 2] = v.z * sc; x[4 * tid + 3] = v.w * sc;
    __syncthreads();
    gemv_chunk(Wo, DIM, x, part, n0, w, lane);
    __syncthreads();
    if (tid < 64) {
        float acc = 0.0f;
        #pragma unroll
        for (int ww = 0; ww < 8; ww++) acc += part[ww * 64 + tid];
        g_omean[b * DIM + n0 + tid] = acc;
    }
}

// ---------------------------------------------------------------------------
// Fused LayerNorm + q GEMV for active rows.  grid (16 n-chunks, 64 slots)
// ---------------------------------------------------------------------------
__global__ __launch_bounds__(256)
void qact_kernel(const float* __restrict__ text,
                 const float* __restrict__ gamma,
                 const float* __restrict__ beta,
                 const float* __restrict__ Wq) {
    __shared__ float x[DIM];
    __shared__ float red[8];
    __shared__ float part[8 * 64];
    int tid = threadIdx.x, lane = tid & 31, w = tid >> 5;
    int n0 = blockIdx.x * 64;
    int nact = g_nact;
    for (int s = blockIdx.y; s < nact; s += gridDim.y) {
        int row = g_act[s];
        float4 v = ((const float4*)(text + (size_t)row * DIM))[tid];
        float sm = v.x + v.y + v.z + v.w;
        float mu = blockReduceSum256(sm, red) * (1.0f / DIM);
        float dx = v.x - mu, dy = v.y - mu, dz = v.z - mu, dw = v.w - mu;
        float var = blockReduceSum256(dx * dx + dy * dy + dz * dz + dw * dw, red) * (1.0f / DIM);
        float inv = rsqrtf(var + EPS);
        float4 g = ((const float4*)gamma)[tid];
        float4 bt = ((const float4*)beta)[tid];
        x[4 * tid + 0] = dx * inv * g.x + bt.x;
        x[4 * tid + 1] = dy * inv * g.y + bt.y;
        x[4 * tid + 2] = dz * inv * g.z + bt.z;
        x[4 * tid + 3] = dw * inv * g.w + bt.w;
        __syncthreads();
        gemv_chunk(Wq, DIM, x, part, n0, w, lane);
        __syncthreads();
        if (tid < 64) {
            float acc = 0.0f;
            #pragma unroll
            for (int ww = 0; ww < 8; ww++) acc += part[ww * 64 + tid];
            g_qact[(size_t)s * DIM + n0 + tid] = acc;
        }
        __syncthreads();
    }
}

// ---------------------------------------------------------------------------
// Segment attention per (slot, head-group of 4 heads). grid (64, 4).
// ---------------------------------------------------------------------------
__global__ __launch_bounds__(256)
void attn_act_kernel() {
    __shared__ float qs[256];
    __shared__ float S[4][M_MEDIA];
    __shared__ float part[8][256];
    int tid = threadIdx.x;
    int lane = tid & 31, w = tid >> 5;
    int hg = blockIdx.y;
    int nact = g_nact;

    for (int s = blockIdx.x; s < nact; s += gridDim.x) {
        int row = g_act[s];
        int b = row >> 11;
        int tt = g_tt[row];
        int j0 = (tt - 1) * M_MEDIA;

        qs[tid] = g_qact[(size_t)s * DIM + hg * 256 + tid];
        __syncthreads();

        // scores: warp w handles 32 j; lane covers 8 c; head = lane>>3
        {
            const float scale = 0.125f;
            int c0 = lane * 8;
            int h = lane >> 3;
            const float* kbase = g_kv + ((size_t)(b * TM_TOT + j0 + w * 32)) * (2 * DIM)
                               + hg * 256 + c0;
            for (int jj = 0; jj < 32; jj++) {
                const float* krow = kbase + (size_t)jj * (2 * DIM);
                float4 k0 = *(const float4*)(krow);
                float4 k1 = *(const float4*)(krow + 4);
                float p = k0.x * qs[c0]     + k0.y * qs[c0 + 1] +
                          k0.z * qs[c0 + 2] + k0.w * qs[c0 + 3] +
                          k1.x * qs[c0 + 4] + k1.y * qs[c0 + 5] +
                          k1.z * qs[c0 + 6] + k1.w * qs[c0 + 7];
                p += __shfl_xor_sync(0xffffffffu, p, 4);
                p += __shfl_xor_sync(0xffffffffu, p, 2);
                p += __shfl_xor_sync(0xffffffffu, p, 1);
                if ((lane & 7) == 0) S[h][w * 32 + jj] = p * scale;
            }
        }
        __syncthreads();

        // softmax: warp 0..3 per local head
        if (w < 4) {
            float vals[8];
            float m = -1e30f;
            #pragma unroll
            for (int k = 0; k < 8; k++) {
                vals[k] = S[w][lane + 32 * k];
                m = fmaxf(m, vals[k]);
            }
            #pragma unroll
            for (int o = 16; o; o >>= 1) m = fmaxf(m, __shfl_xor_sync(0xffffffffu, m, o));
            float sum = 0.0f;
            #pragma unroll
            for (int k = 0; k < 8; k++) { vals[k] = __expf(vals[k] - m); sum += vals[k]; }
            #pragma unroll
            for (int o = 16; o; o >>= 1) sum += __shfl_xor_sync(0xffffffffu, sum, o);
            float inv = 1.0f / sum;
            #pragma unroll
            for (int k = 0; k < 8; k++) S[w][lane + 32 * k] = vals[k] * inv;
        }
        __syncthreads();

        // AV: warp w handles 32 j; lane covers 8 n; head = lane>>3
        {
            int c0 = lane * 8;
            int h = lane >> 3;
            float acc[8] = {0, 0, 0, 0, 0, 0, 0, 0};
            const float* vbase = g_kv + ((size_t)(b * TM_TOT + j0 + w * 32)) * (2 * DIM)
                               + DIM + hg * 256 + c0;
            #pragma unroll 4
            for (int jj = 0; jj < 32; jj++) {
                float p = S[h][w * 32 + jj];
                const float* vr = vbase + (size_t)jj * (2 * DIM);
                float4 v0 = *(const float4*)(vr);
                float4 v1 = *(const float4*)(vr + 4);
                acc[0] = fmaf(p, v0.x, acc[0]); acc[1] = fmaf(p, v0.y, acc[1]);
                acc[2] = fmaf(p, v0.z, acc[2]); acc[3] = fmaf(p, v0.w, acc[3]);
                acc[4] = fmaf(p, v1.x, acc[4]); acc[5] = fmaf(p, v1.y, acc[5]);
                acc[6] = fmaf(p, v1.z, acc[6]); acc[7] = fmaf(p, v1.w, acc[7]);
            }
            #pragma unroll
            for (int u = 0; u < 8; u++) part[w][c0 + u] = acc[u];
        }
        __syncthreads();

        {
            float a = 0.0f;
            #pragma unroll
            for (int ww = 0; ww < 8; ww++) a += part[ww][tid];
            g_oact[(size_t)s * DIM + hg * 256 + tid] = a;
        }
        __syncthreads();
    }
}

// ---------------------------------------------------------------------------
// Fill output: tt==0 -> 0, tt>4 -> omean, active rows skipped
// ---------------------------------------------------------------------------
__global__ void fill_kernel(float* __restrict__ out) {
    int row = blockIdx.x;
    int tt = g_tt[row];
    if (tt >= 1 && tt <= T_MEDIA) return;
    int tid = threadIdx.x;
    int b = row >> 11;
    float4 val = (tt == 0) ? make_float4(0.f, 0.f, 0.f, 0.f)
                           : ((const float4*)(g_omean + b * DIM))[tid];
    ((float4*)(out + (size_t)row * DIM))[tid] = val;
}

// ---------------------------------------------------------------------------
// out GEMV for active rows — parallel warp-split, grid (16, 64)
// ---------------------------------------------------------------------------
__global__ __launch_bounds__(256)
void out_act_kernel(const float* __restrict__ Wo, float* __restrict__ out) {
    __shared__ float x[DIM];
    __shared__ float part[8 * 64];
    int tid = threadIdx.x, lane = tid & 31, w = tid >> 5;
    int n0 = blockIdx.x * 64;
    int nact = g_nact;
    for (int s = blockIdx.y; s < nact; s += gridDim.y) {
        int row = g_act[s];
        ((float4*)x)[tid] = ((const float4*)(g_oact + (size_t)s * DIM))[tid];
        __syncthreads();
        gemv_chunk(Wo, DIM, x, part, n0, w, lane);
        __syncthreads();
        if (tid < 64) {
            float acc = 0.0f;
            #pragma unroll
            for (int ww = 0; ww < 8; ww++) acc += part[ww * 64 + tid];
            out[(size_t)row * DIM + n0 + tid] = acc;
        }
        __syncthreads();
    }
}

// ---------------------------------------------------------------------------
// Launch — two-stream fork/join; GEMM is the 4th submitted launch (profiled).
// ---------------------------------------------------------------------------
extern "C" void kernel_launch(void* const* d_in, const int* in_sizes, int n_in,
                              void* d_out, int out_size) {
    const float* text  = (const float*)d_in[0];
    const float* image = (const float*)d_in[1];
    const int*   loc   = (const int*)d_in[2];
    const float* Wq    = (const float*)d_in[3];
    const float* Wkv   = (const float*)d_in[4];
    const float* Wo    = (const float*)d_in[5];
    const float* gamma = (const float*)d_in[6];
    const float* beta  = (const float*)d_in[7];
    float* out = (float*)d_out;

    static cudaStream_t s2 = nullptr;
    static cudaEvent_t evFork = nullptr, evJoin = nullptr;
    static int inited = 0;
    if (!inited) {
        cudaFuncSetAttribute(gemm_hmma_split,
                             cudaFuncAttributeMaxDynamicSharedMemorySize, SMEM_GEMM);
        cudaStreamCreateWithFlags(&s2, cudaStreamNonBlocking);
        cudaEventCreateWithFlags(&evFork, cudaEventDisableTiming);
        cudaEventCreateWithFlags(&evJoin, cudaEventDisableTiming);
        inited = 1;
    }

    __nv_bfloat16 *img_hi, *img_lo, *wkv_hi, *wkv_lo;
    float *p_kv;
    cudaGetSymbolAddress((void**)&img_hi, g_img_hi);
    cudaGetSymbolAddress((void**)&img_lo, g_img_lo);
    cudaGetSymbolAddress((void**)&wkv_hi, g_Wkv_hi);
    cudaGetSymbolAddress((void**)&wkv_lo, g_Wkv_lo);
    cudaGetSymbolAddress((void**)&p_kv,   g_kv);

    cudaEventRecord(evFork, 0);
    cudaStreamWaitEvent(s2, evFork, 0);

    // main: 1 conv (also zeroes vmean), 2 wtrans
    conv_img<<<(MKV * DIM) / (256 * 4), 256>>>(image);
    wtrans<<<dim3(2 * DIM / 32, DIM / 32), 256>>>(Wkv, wkv_hi, wkv_lo, DIM, 2 * DIM);
    // s2: 3 scan
    scan_kernel<<<BATCH, 1024, 0, s2>>>(loc);
    // main: 4 kv GEMM (profiled) + fused v column sums
    gemm_hmma_split<<<dim3(2 * DIM / GBN, MKV / GBM), 256, SMEM_GEMM>>>(
        img_hi, img_lo, wkv_hi, wkv_lo, p_kv, 2 * DIM);
    // s2: 5 compact, 6 qact
    compact_kernel<<<MQ / 1024, 1024, 0, s2>>>();
    qact_kernel<<<dim3(16, 64), 256, 0, s2>>>(text, gamma, beta, Wq);
    cudaEventRecord(evJoin, s2);

    // main: omean (needs g_vmean from GEMM epilogue)
    omean_kernel<<<dim3(16, BATCH), 256>>>(Wo);

    // join, then dependent tail
    cudaStreamWaitEvent(0, evJoin, 0);
    attn_act_kernel<<<dim3(64, 4), 256>>>();
    fill_kernel<<<MQ, 256>>>(out);
    out_act_kernel<<<dim3(16, 64), 256>>>(Wo, out);
}

// round 12
// speedup vs baseline: 1.7442x; 1.0575x over previous
#include <cuda_runtime.h>
#include <cuda_bf16.h>
#include <math.h>
#include <stdint.h>

// Problem constants
#define BATCH   2
#define NTXT    2048
#define T_MEDIA 4
#define M_MEDIA 256
#define TM_TOT  1024
#define DIM     1024
#define HEADS   16
#define DH      64
#define EPS     1e-5f

#define MQ  (BATCH * NTXT)     // 4096
#define MKV (BATCH * TM_TOT)   // 2048

// ---------------------------------------------------------------------------
// Scratch (device globals; no allocations allowed)
// ---------------------------------------------------------------------------
__device__ __nv_bfloat16 g_img_hi[MKV * DIM];
__device__ __nv_bfloat16 g_img_lo[MKV * DIM];
__device__ __nv_bfloat16 g_Wkv_hi[2 * DIM * DIM];
__device__ __nv_bfloat16 g_Wkv_lo[2 * DIM * DIM];

__device__ float g_kv   [MKV * 2 * DIM];           // k | v (fp32)
__device__ float g_vmean[BATCH * DIM];             // SUM of v cols (scaled later)
__device__ float g_omean[BATCH * DIM];             // (vmean/1024) @ Wo (fp32)
__device__ int   g_tt   [MQ];                      // txt_time
__device__ int   g_act  [MQ];                      // active rows (tt in [1..4])
__device__ int   g_nact;
__device__ float g_qact [MQ * DIM];                // q rows for active queries
__device__ float g_oact [MQ * DIM];                // attention out for active queries

// ---------------------------------------------------------------------------
// PTX helpers (sm_80-baseline only; NO tcgen05 — ptxas target lacks 'a')
// ---------------------------------------------------------------------------
__device__ __forceinline__ uint32_t smem_u32(const void* p) {
    uint32_t a;
    asm("{ .reg .u64 t; cvta.to.shared.u64 t, %1; cvt.u32.u64 %0, t; }" : "=r"(a) : "l"(p));
    return a;
}
__device__ __forceinline__ void cp_async16(uint32_t dst, const void* src) {
    asm volatile("cp.async.cg.shared.global [%0], [%1], 16;\n" :: "r"(dst), "l"(src));
}
__device__ __forceinline__ void ldsm4(uint32_t* r, uint32_t addr) {
    asm volatile("ldmatrix.sync.aligned.m8n8.x4.shared.b16 {%0,%1,%2,%3}, [%4];"
                 : "=r"(r[0]), "=r"(r[1]), "=r"(r[2]), "=r"(r[3]) : "r"(addr));
}
__device__ __forceinline__ void mma16816(float* c, const uint32_t* a,
                                         uint32_t b0, uint32_t b1) {
    asm volatile(
        "mma.sync.aligned.m16n8k16.row.col.f32.bf16.bf16.f32 "
        "{%0,%1,%2,%3}, {%4,%5,%6,%7}, {%8,%9}, {%0,%1,%2,%3};"
        : "+f"(c[0]), "+f"(c[1]), "+f"(c[2]), "+f"(c[3])
        : "r"(a[0]), "r"(a[1]), "r"(a[2]), "r"(a[3]), "r"(b0), "r"(b1));
}
__device__ __forceinline__ uint32_t sw128(uint32_t off) {
    return off ^ ((off >> 3) & 0x70);
}
__device__ __forceinline__ void split2(float v, __nv_bfloat16& h, __nv_bfloat16& l) {
    h = __float2bfloat16(v);
    l = __float2bfloat16(v - __bfloat162float(h));
}

// ---------------------------------------------------------------------------
// Warp-split GEMV core: y[n0..n0+64) = x[0..1024) @ W[.,n0..n0+64)
// ---------------------------------------------------------------------------
__device__ __forceinline__ void gemv_chunk(const float* __restrict__ W, int ldw,
                                           const float* __restrict__ x,
                                           float* __restrict__ part,
                                           int n0, int w, int lane) {
    float a0 = 0.0f, a1 = 0.0f;
    int n = n0 + lane * 2;
    const float* Wp = W + (size_t)(w * 128) * ldw + n;
    const float* xp = x + w * 128;
    #pragma unroll 8
    for (int kk = 0; kk < 128; kk++) {
        float xv = xp[kk];
        float2 wv = *(const float2*)(Wp + (size_t)kk * ldw);
        a0 = fmaf(xv, wv.x, a0);
        a1 = fmaf(xv, wv.y, a1);
    }
    part[w * 64 + lane * 2]     = a0;
    part[w * 64 + lane * 2 + 1] = a1;
}

// ---------------------------------------------------------------------------
// Inclusive scan of locations -> txt_time. One block of 1024 per batch.
// ---------------------------------------------------------------------------
__global__ void scan_kernel(const int* __restrict__ loc) {
    int b = blockIdx.x;
    int tid = threadIdx.x;
    if (b == 0 && tid == 0) g_nact = 0;
    __shared__ int s[1024];
    const int* L = loc + b * NTXT;
    int a0 = L[2 * tid];
    int a1 = L[2 * tid + 1];
    int v0 = a0, v1 = a0 + a1;
    s[tid] = v1;
    __syncthreads();
    for (int off = 1; off < 1024; off <<= 1) {
        int t = (tid >= off) ? s[tid - off] : 0;
        __syncthreads();
        s[tid] += t;
        __syncthreads();
    }
    int excl = s[tid] - v1;
    g_tt[b * NTXT + 2 * tid]     = excl + v0;
    g_tt[b * NTXT + 2 * tid + 1] = excl + v1;
}

__global__ void compact_kernel() {
    int row = blockIdx.x * 1024 + threadIdx.x;
    int tt = g_tt[row];
    if (tt >= 1 && tt <= T_MEDIA) {
        int slot = atomicAdd(&g_nact, 1);
        g_act[slot] = row;
    }
}

// ---------------------------------------------------------------------------
// Block reduce helper (256 threads)
// ---------------------------------------------------------------------------
__device__ __forceinline__ float blockReduceSum256(float v, float* red) {
    #pragma unroll
    for (int o = 16; o; o >>= 1) v += __shfl_xor_sync(0xffffffffu, v, o);
    int lane = threadIdx.x & 31, w = threadIdx.x >> 5;
    if (lane == 0) red[w] = v;
    __syncthreads();
    float r = (threadIdx.x < 8) ? red[threadIdx.x] : 0.0f;
    if (threadIdx.x < 32) {
        #pragma unroll
        for (int o = 4; o; o >>= 1) r += __shfl_xor_sync(0xffffffffu, r, o);
        if (threadIdx.x == 0) red[0] = r;
    }
    __syncthreads();
    float out = red[0];
    __syncthreads();
    return out;
}

// ---------------------------------------------------------------------------
// image fp32 -> hi/lo bf16 (elementwise).  Also zeroes g_vmean (blocks 0..7),
// which runs before the GEMM's epilogue atomics on the same stream.
// ---------------------------------------------------------------------------
__global__ void conv_img(const float* __restrict__ img) {
    if (blockIdx.x < 8) g_vmean[blockIdx.x * 256 + threadIdx.x] = 0.0f;
    size_t i = ((size_t)blockIdx.x * 256 + threadIdx.x) * 4;
    float4 v = *(const float4*)(img + i);
    __nv_bfloat16 h[4], l[4];
    split2(v.x, h[0], l[0]); split2(v.y, h[1], l[1]);
    split2(v.z, h[2], l[2]); split2(v.w, h[3], l[3]);
    *(__nv_bfloat162*)(g_img_hi + i)     = __nv_bfloat162(h[0], h[1]);
    *(__nv_bfloat162*)(g_img_hi + i + 2) = __nv_bfloat162(h[2], h[3]);
    *(__nv_bfloat162*)(g_img_lo + i)     = __nv_bfloat162(l[0], l[1]);
    *(__nv_bfloat162*)(g_img_lo + i + 2) = __nv_bfloat162(l[2], l[3]);
}

// ---------------------------------------------------------------------------
// Wkv [K,N] fp32 -> W^T [N,K] hi/lo bf16 (tiled transpose)
// ---------------------------------------------------------------------------
__global__ void wtrans(const float* __restrict__ W,
                       __nv_bfloat16* __restrict__ Thi,
                       __nv_bfloat16* __restrict__ Tlo,
                       int Kd, int Nd) {
    __shared__ float t[32][33];
    int bx = blockIdx.x * 32;
    int by = blockIdx.y * 32;
    int x = threadIdx.x & 31, y4 = (threadIdx.x >> 5) * 4;
    #pragma unroll
    for (int i = 0; i < 4; i++)
        t[y4 + i][x] = W[(size_t)(by + y4 + i) * Nd + bx + x];
    __syncthreads();
    #pragma unroll
    for (int i = 0; i < 4; i++) {
        float v = t[x][y4 + i];
        __nv_bfloat16 h, l;
        split2(v, h, l);
        size_t o = (size_t)(bx + y4 + i) * Kd + by + x;
        Thi[o] = h;
        Tlo[o] = l;
    }
}

// ---------------------------------------------------------------------------
// bf16 split GEMM via mma.sync (HMMA), 4-stage cp.async pipeline,
// ONE barrier per ktile (issue-after-compute removes the WAR hazard).
// CTA tile 128x256, 8 warps at 64x64 each.  K' = 3K split.
// v-half CTAs (col0 >= DIM) accumulate column sums into g_vmean (atomics).
// ---------------------------------------------------------------------------
#define GBM 128
#define GBN 256
#define GBK 64
#define KTILES 48
#define ABYTES (GBM * GBK * 2)                // 16384
#define BBYTES (GBN * GBK * 2)                // 32768
#define STG    4
#define SMEM_GEMM (STG * (ABYTES + BBYTES))   // 196608

__global__ __launch_bounds__(256, 1)
void gemm_hmma_split(const __nv_bfloat16* __restrict__ A_hi,
                     const __nv_bfloat16* __restrict__ A_lo,
                     const __nv_bfloat16* __restrict__ B_hi,
                     const __nv_bfloat16* __restrict__ B_lo,
                     float* __restrict__ C, int N) {
    extern __shared__ char smem[];
    const int K = 1024;
    uint32_t sb = smem_u32(smem);
    int tid = threadIdx.x;
    int lane = tid & 31, wid = tid >> 5;
    int row0 = blockIdx.y * GBM, col0 = blockIdx.x * GBN;

    int lr = tid >> 3;            // 0..31
    int lc = tid & 7;             // 0..7 (16B chunk in 128B row)

    int wm = wid >> 2, wn = wid & 3;       // 2 x 4 warp grid
    int m_warp = wm * 64, n_warp = wn * 64;
    int a_row = lane & 15;
    int a_colb = (lane >> 4) * 8;
    int b_row = (lane & 7) + 8 * ((lane >> 4) & 1);
    int b_colb = 8 * ((lane >> 3) & 1);

    float acc[4][8][4];
    #pragma unroll
    for (int i = 0; i < 4; i++)
        #pragma unroll
        for (int j = 0; j < 8; j++)
            #pragma unroll
            for (int q = 0; q < 4; q++) acc[i][j][q] = 0.0f;

    auto issue = [&](int kt) {
        int term = kt >> 4;
        int ks = (kt & 15) * GBK;
        uint32_t abase = sb + (uint32_t)((kt % STG) * (ABYTES + BBYTES));
        uint32_t bbase = abase + ABYTES;
        const __nv_bfloat16* Ag = (term < 2) ? A_hi : A_lo;
        const __nv_bfloat16* Bg = (term == 1) ? B_lo : B_hi;
        #pragma unroll
        for (int j = 0; j < 4; j++) {
            int r = lr + 32 * j;
            uint32_t off = (uint32_t)(r * 128 + lc * 16);
            cp_async16(abase + sw128(off),
                       Ag + (size_t)(row0 + r) * K + ks + lc * 8);
        }
        #pragma unroll
        for (int j = 0; j < 8; j++) {
            int r = lr + 32 * j;
            uint32_t off = (uint32_t)(r * 128 + lc * 16);
            cp_async16(bbase + sw128(off),
                       Bg + (size_t)(col0 + r) * K + ks + lc * 8);
        }
        asm volatile("cp.async.commit_group;" ::: "memory");
    };

    issue(0);
    issue(1);
    issue(2);

    #pragma unroll 1
    for (int kt = 0; kt < KTILES; kt++) {
        // groups issued so far: 0..kt+2 ; wait for 0..kt to complete
        if (kt + 1 < KTILES) {
            asm volatile("cp.async.wait_group 2;" ::: "memory");
        } else {
            asm volatile("cp.async.wait_group 0;" ::: "memory");
        }
        __syncthreads();   // single barrier: visibility + proves compute(kt-1) done

        uint32_t ab = sb + (uint32_t)((kt % STG) * (ABYTES + BBYTES));
        uint32_t bb = ab + ABYTES;
        #pragma unroll
        for (int k16 = 0; k16 < 4; k16++) {
            uint32_t a_r[4][4], b_r[4][4];
            #pragma unroll
            for (int mf = 0; mf < 4; mf++) {
                uint32_t off = (uint32_t)((m_warp + mf * 16 + a_row) * 128 +
                                          (k16 * 16 + a_colb) * 2);
                ldsm4(a_r[mf], ab + sw128(off));
            }
            #pragma unroll
            for (int nf2 = 0; nf2 < 4; nf2++) {
                uint32_t off = (uint32_t)((n_warp + nf2 * 16 + b_row) * 128 +
                                          (k16 * 16 + b_colb) * 2);
                ldsm4(b_r[nf2], bb + sw128(off));
            }
            #pragma unroll
            for (int mf = 0; mf < 4; mf++)
                #pragma unroll
                for (int nf = 0; nf < 8; nf++) {
                    const uint32_t* b2 = &b_r[nf >> 1][(nf & 1) * 2];
                    mma16816(acc[mf][nf], a_r[mf], b2[0], b2[1]);
                }
        }

        // issue next tile AFTER compute: writes buffer (kt+3)%4, last read at
        // iter kt-1; the barrier above proves all warps finished that read.
        if (kt + 3 < KTILES) issue(kt + 3);
    }

    // ---- epilogue: store C ----
    int r_base = row0 + m_warp + (lane >> 2);
    int c_base = col0 + n_warp + 2 * (lane & 3);
    #pragma unroll
    for (int mf = 0; mf < 4; mf++)
        #pragma unroll
        for (int nf = 0; nf < 8; nf++) {
            float* p = C + (size_t)(r_base + mf * 16) * N + c_base + nf * 8;
            *(float2*)p = make_float2(acc[mf][nf][0], acc[mf][nf][1]);
            *(float2*)(p + (size_t)8 * N) = make_float2(acc[mf][nf][2], acc[mf][nf][3]);
        }

    // ---- fused v column sums (only v half: col0 >= DIM) ----
    if (col0 >= DIM) {
        int b = row0 >> 10;
        #pragma unroll
        for (int nf = 0; nf < 8; nf++) {
            float c0s = 0.0f, c1s = 0.0f;
            #pragma unroll
            for (int mf = 0; mf < 4; mf++) {
                c0s += acc[mf][nf][0] + acc[mf][nf][2];
                c1s += acc[mf][nf][1] + acc[mf][nf][3];
            }
            #pragma unroll
            for (int o = 4; o <= 16; o <<= 1) {
                c0s += __shfl_xor_sync(0xffffffffu, c0s, o);
                c1s += __shfl_xor_sync(0xffffffffu, c1s, o);
            }
            if ((lane >> 2) == 0) {
                int c = c_base + nf * 8 - DIM;
                atomicAdd(&g_vmean[b * DIM + c], c0s);
                atomicAdd(&g_vmean[b * DIM + c + 1], c1s);
            }
        }
    }
}

// ---------------------------------------------------------------------------
// omean[b] = (vmean[b]/TM_TOT) @ Wo  — parallel warp-split GEMV, grid (16, BATCH)
// ---------------------------------------------------------------------------
__global__ __launch_bounds__(256)
void omean_kernel(const float* __restrict__ Wo) {
    __shared__ float x[DIM];
    __shared__ float part[8 * 64];
    int tid = threadIdx.x, lane = tid & 31, w = tid >> 5;
    int n0 = blockIdx.x * 64;
    int b = blockIdx.y;
    float4 v = ((const float4*)(g_vmean + b * DIM))[tid];
    const float sc = 1.0f / TM_TOT;
    x[4 * tid + 0] = v.x * sc; x[4 * tid + 1] = v.y * sc;
    x[4 * tid + 2] = v.z * sc; x[4 * tid + 3] = v.w * sc;
    __syncthreads();
    gemv_chunk(Wo, DIM, x, part, n0, w, lane);
    __syncthreads();
    if (tid < 64) {
        float acc = 0.0f;
        #pragma unroll
        for (int ww = 0; ww < 8; ww++) acc += part[ww * 64 + tid];
        g_omean[b * DIM + n0 + tid] = acc;
    }
}

// ---------------------------------------------------------------------------
// Fused LayerNorm + q GEMV for active rows.  grid (16 n-chunks, 64 slots)
// ---------------------------------------------------------------------------
__global__ __launch_bounds__(256)
void qact_kernel(const float* __restrict__ text,
                 const float* __restrict__ gamma,
                 const float* __restrict__ beta,
                 const float* __restrict__ Wq) {
    __shared__ float x[DIM];
    __shared__ float red[8];
    __shared__ float part[8 * 64];
    int tid = threadIdx.x, lane = tid & 31, w = tid >> 5;
    int n0 = blockIdx.x * 64;
    int nact = g_nact;
    for (int s = blockIdx.y; s < nact; s += gridDim.y) {
        int row = g_act[s];
        float4 v = ((const float4*)(text + (size_t)row * DIM))[tid];
        float sm = v.x + v.y + v.z + v.w;
        float mu = blockReduceSum256(sm, red) * (1.0f / DIM);
        float dx = v.x - mu, dy = v.y - mu, dz = v.z - mu, dw = v.w - mu;
        float var = blockReduceSum256(dx * dx + dy * dy + dz * dz + dw * dw, red) * (1.0f / DIM);
        float inv = rsqrtf(var + EPS);
        float4 g = ((const float4*)gamma)[tid];
        float4 bt = ((const float4*)beta)[tid];
        x[4 * tid + 0] = dx * inv * g.x + bt.x;
        x[4 * tid + 1] = dy * inv * g.y + bt.y;
        x[4 * tid + 2] = dz * inv * g.z + bt.z;
        x[4 * tid + 3] = dw * inv * g.w + bt.w;
        __syncthreads();
        gemv_chunk(Wq, DIM, x, part, n0, w, lane);
        __syncthreads();
        if (tid < 64) {
            float acc = 0.0f;
            #pragma unroll
            for (int ww = 0; ww < 8; ww++) acc += part[ww * 64 + tid];
            g_qact[(size_t)s * DIM + n0 + tid] = acc;
        }
        __syncthreads();
    }
}

// ---------------------------------------------------------------------------
// Segment attention per (slot, head-group of 4 heads). grid (64, 4).
// ---------------------------------------------------------------------------
__global__ __launch_bounds__(256)
void attn_act_kernel() {
    __shared__ float qs[256];
    __shared__ float S[4][M_MEDIA];
    __shared__ float part[8][256];
    int tid = threadIdx.x;
    int lane = tid & 31, w = tid >> 5;
    int hg = blockIdx.y;
    int nact = g_nact;

    for (int s = blockIdx.x; s < nact; s += gridDim.x) {
        int row = g_act[s];
        int b = row >> 11;
        int tt = g_tt[row];
        int j0 = (tt - 1) * M_MEDIA;

        qs[tid] = g_qact[(size_t)s * DIM + hg * 256 + tid];
        __syncthreads();

        // scores: warp w handles 32 j; lane covers 8 c; head = lane>>3
        {
            const float scale = 0.125f;
            int c0 = lane * 8;
            int h = lane >> 3;
            const float* kbase = g_kv + ((size_t)(b * TM_TOT + j0 + w * 32)) * (2 * DIM)
                               + hg * 256 + c0;
            for (int jj = 0; jj < 32; jj++) {
                const float* krow = kbase + (size_t)jj * (2 * DIM);
                float4 k0 = *(const float4*)(krow);
                float4 k1 = *(const float4*)(krow + 4);
                float p = k0.x * qs[c0]     + k0.y * qs[c0 + 1] +
                          k0.z * qs[c0 + 2] + k0.w * qs[c0 + 3] +
                          k1.x * qs[c0 + 4] + k1.y * qs[c0 + 5] +
                          k1.z * qs[c0 + 6] + k1.w * qs[c0 + 7];
                p += __shfl_xor_sync(0xffffffffu, p, 4);
                p += __shfl_xor_sync(0xffffffffu, p, 2);
                p += __shfl_xor_sync(0xffffffffu, p, 1);
                if ((lane & 7) == 0) S[h][w * 32 + jj] = p * scale;
            }
        }
        __syncthreads();

        // softmax: warp 0..3 per local head
        if (w < 4) {
            float vals[8];
            float m = -1e30f;
            #pragma unroll
            for (int k = 0; k < 8; k++) {
                vals[k] = S[w][lane + 32 * k];
                m = fmaxf(m, vals[k]);
            }
            #pragma unroll
            for (int o = 16; o; o >>= 1) m = fmaxf(m, __shfl_xor_sync(0xffffffffu, m, o));
            float sum = 0.0f;
            #pragma unroll
            for (int k = 0; k < 8; k++) { vals[k] = __expf(vals[k] - m); sum += vals[k]; }
            #pragma unroll
            for (int o = 16; o; o >>= 1) sum += __shfl_xor_sync(0xffffffffu, sum, o);
            float inv = 1.0f / sum;
            #pragma unroll
            for (int k = 0; k < 8; k++) S[w][lane + 32 * k] = vals[k] * inv;
        }
        __syncthreads();

        // AV: warp w handles 32 j; lane covers 8 n; head = lane>>3
        {
            int c0 = lane * 8;
            int h = lane >> 3;
            float acc[8] = {0, 0, 0, 0, 0, 0, 0, 0};
            const float* vbase = g_kv + ((size_t)(b * TM_TOT + j0 + w * 32)) * (2 * DIM)
                               + DIM + hg * 256 + c0;
            #pragma unroll 4
            for (int jj = 0; jj < 32; jj++) {
                float p = S[h][w * 32 + jj];
                const float* vr = vbase + (size_t)jj * (2 * DIM);
                float4 v0 = *(const float4*)(vr);
                float4 v1 = *(const float4*)(vr + 4);
                acc[0] = fmaf(p, v0.x, acc[0]); acc[1] = fmaf(p, v0.y, acc[1]);
                acc[2] = fmaf(p, v0.z, acc[2]); acc[3] = fmaf(p, v0.w, acc[3]);
                acc[4] = fmaf(p, v1.x, acc[4]); acc[5] = fmaf(p, v1.y, acc[5]);
                acc[6] = fmaf(p, v1.z, acc[6]); acc[7] = fmaf(p, v1.w, acc[7]);
            }
            #pragma unroll
            for (int u = 0; u < 8; u++) part[w][c0 + u] = acc[u];
        }
        __syncthreads();

        {
            float a = 0.0f;
            #pragma unroll
            for (int ww = 0; ww < 8; ww++) a += part[ww][tid];
            g_oact[(size_t)s * DIM + hg * 256 + tid] = a;
        }
        __syncthreads();
    }
}

// ---------------------------------------------------------------------------
// Fill output: tt==0 -> 0, tt>4 -> omean, active rows skipped
// ---------------------------------------------------------------------------
__global__ void fill_kernel(float* __restrict__ out) {
    int row = blockIdx.x;
    int tt = g_tt[row];
    if (tt >= 1 && tt <= T_MEDIA) return;
    int tid = threadIdx.x;
    int b = row >> 11;
    float4 val = (tt == 0) ? make_float4(0.f, 0.f, 0.f, 0.f)
                           : ((const float4*)(g_omean + b * DIM))[tid];
    ((float4*)(out + (size_t)row * DIM))[tid] = val;
}

// ---------------------------------------------------------------------------
// out GEMV for active rows — parallel warp-split, grid (16, 64)
// ---------------------------------------------------------------------------
__global__ __launch_bounds__(256)
void out_act_kernel(const float* __restrict__ Wo, float* __restrict__ out) {
    __shared__ float x[DIM];
    __shared__ float part[8 * 64];
    int tid = threadIdx.x, lane = tid & 31, w = tid >> 5;
    int n0 = blockIdx.x * 64;
    int nact = g_nact;
    for (int s = blockIdx.y; s < nact; s += gridDim.y) {
        int row = g_act[s];
        ((float4*)x)[tid] = ((const float4*)(g_oact + (size_t)s * DIM))[tid];
        __syncthreads();
        gemv_chunk(Wo, DIM, x, part, n0, w, lane);
        __syncthreads();
        if (tid < 64) {
            float acc = 0.0f;
            #pragma unroll
            for (int ww = 0; ww < 8; ww++) acc += part[ww * 64 + tid];
            out[(size_t)row * DIM + n0 + tid] = acc;
        }
        __syncthreads();
    }
}

// ---------------------------------------------------------------------------
// Launch — two-stream fork/join; wtrans overlaps conv_img, qact overlaps GEMM.
// ---------------------------------------------------------------------------
extern "C" void kernel_launch(void* const* d_in, const int* in_sizes, int n_in,
                              void* d_out, int out_size) {
    const float* text  = (const float*)d_in[0];
    const float* image = (const float*)d_in[1];
    const int*   loc   = (const int*)d_in[2];
    const float* Wq    = (const float*)d_in[3];
    const float* Wkv   = (const float*)d_in[4];
    const float* Wo    = (const float*)d_in[5];
    const float* gamma = (const float*)d_in[6];
    const float* beta  = (const float*)d_in[7];
    float* out = (float*)d_out;

    static cudaStream_t s2 = nullptr;
    static cudaEvent_t evFork = nullptr, evW = nullptr, evJoin = nullptr;
    static int inited = 0;
    if (!inited) {
        cudaFuncSetAttribute(gemm_hmma_split,
                             cudaFuncAttributeMaxDynamicSharedMemorySize, SMEM_GEMM);
        cudaStreamCreateWithFlags(&s2, cudaStreamNonBlocking);
        cudaEventCreateWithFlags(&evFork, cudaEventDisableTiming);
        cudaEventCreateWithFlags(&evW, cudaEventDisableTiming);
        cudaEventCreateWithFlags(&evJoin, cudaEventDisableTiming);
        inited = 1;
    }

    __nv_bfloat16 *img_hi, *img_lo, *wkv_hi, *wkv_lo;
    float *p_kv;
    cudaGetSymbolAddress((void**)&img_hi, g_img_hi);
    cudaGetSymbolAddress((void**)&img_lo, g_img_lo);
    cudaGetSymbolAddress((void**)&wkv_hi, g_Wkv_hi);
    cudaGetSymbolAddress((void**)&wkv_lo, g_Wkv_lo);
    cudaGetSymbolAddress((void**)&p_kv,   g_kv);

    cudaEventRecord(evFork, 0);
    cudaStreamWaitEvent(s2, evFork, 0);

    // s2: wtrans (feeds GEMM), then the q-branch (overlaps GEMM)
    wtrans<<<dim3(2 * DIM / 32, DIM / 32), 256, 0, s2>>>(Wkv, wkv_hi, wkv_lo, DIM, 2 * DIM);
    cudaEventRecord(evW, s2);
    scan_kernel<<<BATCH, 1024, 0, s2>>>(loc);
    compact_kernel<<<MQ / 1024, 1024, 0, s2>>>();
    qact_kernel<<<dim3(16, 64), 256, 0, s2>>>(text, gamma, beta, Wq);
    cudaEventRecord(evJoin, s2);

    // main: conv (also zeroes vmean), then GEMM (needs wtrans), then omean
    conv_img<<<(MKV * DIM) / (256 * 4), 256>>>(image);
    cudaStreamWaitEvent(0, evW, 0);
    gemm_hmma_split<<<dim3(2 * DIM / GBN, MKV / GBM), 256, SMEM_GEMM>>>(
        img_hi, img_lo, wkv_hi, wkv_lo, p_kv, 2 * DIM);
    omean_kernel<<<dim3(16, BATCH), 256>>>(Wo);

    // join, then dependent tail
    cudaStreamWaitEvent(0, evJoin, 0);
    attn_act_kernel<<<dim3(64, 4), 256>>>();
    fill_kernel<<<MQ, 256>>>(out);
    out_act_kernel<<<dim3(16, 64), 256>>>(Wo, out);
}